// round 13
// baseline (speedup 1.0000x reference)
#include <cuda_runtime.h>
#include <cuda_fp16.h>
#include <math.h>
#include <stdint.h>

// ---------------- problem constants ----------------
#define BATCH   2
#define SEQ     2048
#define BT      (BATCH*SEQ)      // 4096 rows
#define DMODEL  768
#define DINNER  1536
#define NHEADS  24
#define DHEAD   64
#define DSTATE  8
#define DCONV   4
#define DPROJ   3120             // 2*DINNER + NHEADS*2
#define DFF     3072

// transposed weight scratch offsets (halves); layout [N][K]
#define W_IN_OFF  0
#define W_BC_OFF  2396160                       // 768*3120
#define W_OUT_OFF 2985984                       // + 1536*384
#define FF1_OFF   4165632                       // + 1536*768
#define FF2_OFF   6524928                       // + 768*3072
#define W_TOTAL   8884224                       // + 3072*768

// merged-transpose tile ranges (32x32 tiles, Nt = tiles along N)
#define T1_END 2352      // w_in : 98*24
#define T2_END 2928      // w_bc : 12*48
#define T3_END 4080      // w_out: 24*48
#define T4_END 6384      // ff1  : 96*24
#define T5_END 8688      // ff2  : 24*96

// ---------------- scratch (static device globals; no allocation) ----------------
__device__ float  g_proj[BT*DPROJ];
__device__ float  g_bc  [BT*2*NHEADS*DSTATE];
__device__ float  g_x1  [BT*DMODEL];
__device__ __half g_xnh [BT*DMODEL];
__device__ __half g_vh  [BT*DINNER];
__device__ __half g_yh  [BT*DINNER];
__device__ __half g_hh  [BT*DMODEL];
__device__ __half g_ffh [BT*DFF];
__device__ __half g_wh  [W_TOTAL];

// ---------------- device math helpers ----------------
__device__ __forceinline__ float sigmoidf_(float x) { return 1.0f / (1.0f + expf(-x)); }
__device__ __forceinline__ float siluf_(float x)    { return x * sigmoidf_(x); }
__device__ __forceinline__ float softplusf_(float x){ return fmaxf(x, 0.0f) + log1pf(expf(-fabsf(x))); }
__device__ __forceinline__ float geluf_(float x) {
    float x3 = x * x * x;
    float t  = tanhf(0.7978845608028654f * (x + 0.044715f * x3));
    return 0.5f * x * (1.0f + t);
}

// ---------------- merged transpose+convert: all 5 weights, one launch --------
__global__ void transpose_all_kernel(const float* __restrict__ w_in,
                                     const float* __restrict__ w_bc,
                                     const float* __restrict__ w_out,
                                     const float* __restrict__ ff1,
                                     const float* __restrict__ ff2,
                                     __half* __restrict__ wh) {
    __shared__ float tile[32][33];
    int id = blockIdx.x;
    const float* src; __half* dst; int K, N, Nt;
    if (id < T1_END)      {            src = w_in;  dst = wh + W_IN_OFF;  K = DMODEL; N = DPROJ; Nt = 98; }
    else if (id < T2_END) { id -= T1_END; src = w_bc;  dst = wh + W_BC_OFF;  K = DINNER; N = 384;   Nt = 12; }
    else if (id < T3_END) { id -= T2_END; src = w_out; dst = wh + W_OUT_OFF; K = DINNER; N = DMODEL;Nt = 24; }
    else if (id < T4_END) { id -= T3_END; src = ff1;   dst = wh + FF1_OFF;   K = DMODEL; N = DFF;   Nt = 96; }
    else                  { id -= T4_END; src = ff2;   dst = wh + FF2_OFF;   K = DFF;    N = DMODEL;Nt = 24; }
    int nb = (id % Nt) * 32, kb = (id / Nt) * 32;
    int tx = threadIdx.x, ty = threadIdx.y;   // 32 x 8
#pragma unroll
    for (int j = 0; j < 32; j += 8) {
        int k = kb + ty + j, n = nb + tx;
        tile[ty + j][tx] = (k < K && n < N) ? src[(size_t)k * N + n] : 0.0f;
    }
    __syncthreads();
#pragma unroll
    for (int j = 0; j < 32; j += 8) {
        int n = nb + ty + j, k = kb + tx;
        if (n < N && k < K) dst[(size_t)n * K + k] = __float2half(tile[tx][ty + j]);
    }
}

// ---------------- rmsnorm: one block per row, fp16 output ----------------
__global__ void rmsnorm_kernel(const float* __restrict__ x,
                               const float* __restrict__ w,
                               __half* __restrict__ out) {
    int row = blockIdx.x;
    const float* xr = x + (size_t)row * DMODEL;
    __half*    orow = out + (size_t)row * DMODEL;

    float xv[3];
    float ss = 0.0f;
#pragma unroll
    for (int j = 0; j < 3; j++) {
        int i = threadIdx.x + j * 256;
        float v = xr[i];
        xv[j] = v;
        ss += v * v;
    }
#pragma unroll
    for (int off = 16; off > 0; off >>= 1)
        ss += __shfl_xor_sync(0xffffffff, ss, off);
    __shared__ float sh[8];
    int lane = threadIdx.x & 31, wid = threadIdx.x >> 5;
    if (lane == 0) sh[wid] = ss;
    __syncthreads();
    if (wid == 0) {
        float v = (lane < 8) ? sh[lane] : 0.0f;
#pragma unroll
        for (int off = 4; off > 0; off >>= 1)
            v += __shfl_xor_sync(0xffffffff, v, off);
        if (lane == 0) sh[0] = rsqrtf(v * (1.0f / DMODEL) + 1e-6f);
    }
    __syncthreads();
    float s = sh[0];
#pragma unroll
    for (int j = 0; j < 3; j++) {
        int i = threadIdx.x + j * 256;
        orow[i] = __float2half(xv[j] * s * w[i]);
    }
}

// ============================================================================
// fp16 mma.sync GEMM (m16n8k16), 3-stage cp.async pipeline, dynamic smem.
//   C[M,N] = A[M,K] @ Bt[N,K]^T ; A,Bt fp16, accumulate fp32.
//   BM=128, BK=32, 256 threads (8 warps).
//   BN=128: warp grid 2x4, tile 64x32 | BN=64: warp grid 4x2, tile 32x32.
//   smem rows padded to 40 halves (80B) -> ldmatrix conflict-free.
//   EPI: 0 none(f32) | 1 half(gelu(acc+bias)) | 2 f32 acc+bias+res
//        | 3 f32 acc+res | 4 f32, silu applied when col < DINNER (proj gate)
// ============================================================================
#define ASTRH  40
#define STAGES 3

template <int BN, int WM, int WN, int EPI>
__global__ void __launch_bounds__(256)
gemm_fp16(const __half* __restrict__ A,
          const __half* __restrict__ Bt,
          void* __restrict__ Cv,
          int M, int N, int K,
          const float* __restrict__ bias,
          const float* __restrict__ res) {
    constexpr int MT   = WM / 16;
    constexpr int NT   = WN / 8;
    constexpr int WGM  = 128 / WM;
    constexpr int ASTG = 128 * ASTRH;
    constexpr int BSTG = BN * ASTRH;
    constexpr int BCH  = (BN * 4) / 256;

    extern __shared__ __half dsm[];
    __half* As = dsm;
    __half* Bs = dsm + STAGES * ASTG;

    const int tid  = threadIdx.x;
    const int warp = tid >> 5;
    const int lane = tid & 31;
    const int g    = lane >> 2;
    const int t    = lane & 3;
    const int sel  = lane >> 3;

    const int wm = (warp % WGM) * WM;
    const int wn = (warp / WGM) * WN;
    const int bm = blockIdx.y * 128;
    const int bn = blockIdx.x * BN;

    const int lrow  = wm + ((sel & 1) << 3) + (lane & 7);
    const int lcolh = (sel >> 1) << 3;
    const int brow  = ((sel >> 1) << 3) + (lane & 7);
    const int bcolh = (sel & 1) << 3;

    const uint32_t as0 = (uint32_t)__cvta_generic_to_shared(As);
    const uint32_t bs0 = (uint32_t)__cvta_generic_to_shared(Bs);

    float acc[MT][NT][4];
#pragma unroll
    for (int i = 0; i < MT; i++)
#pragma unroll
        for (int j = 0; j < NT; j++)
#pragma unroll
            for (int r = 0; r < 4; r++) acc[i][j][r] = 0.0f;

    const int nkt = K >> 5;

    auto issue = [&](int kt, int buf) {
        int k0 = kt << 5;
#pragma unroll
        for (int i = 0; i < 2; i++) {
            int idx = tid + (i << 8);
            int row = idx >> 2, c16 = idx & 3;
            const __half* src = &A[(size_t)(bm + row) * K + k0 + c16 * 8];
            uint32_t dst = as0 + (uint32_t)(buf * ASTG + row * ASTRH + c16 * 8) * 2u;
            asm volatile("cp.async.cg.shared.global [%0], [%1], 16;"
                         :: "r"(dst), "l"(src));
        }
#pragma unroll
        for (int i = 0; i < BCH; i++) {
            int idx = tid + (i << 8);
            int row = idx >> 2, c16 = idx & 3;
            int n = bn + row;
            const __half* src = &Bt[(size_t)(n < N ? n : 0) * K + k0 + c16 * 8];
            int sz = (n < N) ? 16 : 0;
            uint32_t dst = bs0 + (uint32_t)(buf * BSTG + row * ASTRH + c16 * 8) * 2u;
            asm volatile("cp.async.cg.shared.global [%0], [%1], 16, %2;"
                         :: "r"(dst), "l"(src), "r"(sz));
        }
        asm volatile("cp.async.commit_group;" ::: "memory");
    };

#pragma unroll
    for (int s = 0; s < STAGES - 1; ++s)
        if (s < nkt) issue(s, s);

    int buf = 0;
    for (int kt = 0; kt < nkt; ++kt) {
        asm volatile("cp.async.wait_group %0;" :: "n"(STAGES - 2) : "memory");
        __syncthreads();
        if (kt + STAGES - 1 < nkt)
            issue(kt + STAGES - 1, (kt + STAGES - 1) % STAGES);

#pragma unroll
        for (int ks = 0; ks < 2; ks++) {
            uint32_t a[MT][4];
#pragma unroll
            for (int mi = 0; mi < MT; mi++) {
                uint32_t addr = as0 + (uint32_t)(buf * ASTG +
                                (lrow + mi * 16) * ASTRH + ks * 16 + lcolh) * 2u;
                asm volatile(
                    "ldmatrix.sync.aligned.m8n8.x4.shared.b16 {%0,%1,%2,%3}, [%4];"
                    : "=r"(a[mi][0]), "=r"(a[mi][1]), "=r"(a[mi][2]), "=r"(a[mi][3])
                    : "r"(addr));
            }
            uint32_t b[NT][2];
#pragma unroll
            for (int nt2 = 0; nt2 < NT / 2; nt2++) {
                uint32_t addr = bs0 + (uint32_t)(buf * BSTG +
                                (wn + nt2 * 16 + brow) * ASTRH + ks * 16 + bcolh) * 2u;
                asm volatile(
                    "ldmatrix.sync.aligned.m8n8.x4.shared.b16 {%0,%1,%2,%3}, [%4];"
                    : "=r"(b[nt2 * 2][0]), "=r"(b[nt2 * 2][1]),
                      "=r"(b[nt2 * 2 + 1][0]), "=r"(b[nt2 * 2 + 1][1])
                    : "r"(addr));
            }
#pragma unroll
            for (int ni = 0; ni < NT; ni++)
#pragma unroll
                for (int mi = 0; mi < MT; mi++) {
                    asm volatile(
                        "mma.sync.aligned.m16n8k16.row.col.f32.f16.f16.f32 "
                        "{%0,%1,%2,%3},{%4,%5,%6,%7},{%8,%9},{%0,%1,%2,%3};"
                        : "+f"(acc[mi][ni][0]), "+f"(acc[mi][ni][1]),
                          "+f"(acc[mi][ni][2]), "+f"(acc[mi][ni][3])
                        : "r"(a[mi][0]), "r"(a[mi][1]), "r"(a[mi][2]), "r"(a[mi][3]),
                          "r"(b[ni][0]), "r"(b[ni][1]));
                }
        }
        buf = (buf + 1 == STAGES) ? 0 : buf + 1;
    }

    // ---- epilogue ----
    float*  Cf = (float*)Cv;
    __half* Ch = (__half*)Cv;
#pragma unroll
    for (int mi = 0; mi < MT; mi++) {
        int row0 = bm + wm + mi * 16 + g;
        int row1 = row0 + 8;
#pragma unroll
        for (int ni = 0; ni < NT; ni++) {
            int col = bn + wn + ni * 8 + 2 * t;
            if (col < N) {
                float2 p0 = make_float2(acc[mi][ni][0], acc[mi][ni][1]);
                float2 p1 = make_float2(acc[mi][ni][2], acc[mi][ni][3]);
                if (EPI == 1) {
                    float b0v = bias[col], b1v = bias[col + 1];
                    *reinterpret_cast<__half2*>(&Ch[(size_t)row0 * N + col]) =
                        __floats2half2_rn(geluf_(p0.x + b0v), geluf_(p0.y + b1v));
                    *reinterpret_cast<__half2*>(&Ch[(size_t)row1 * N + col]) =
                        __floats2half2_rn(geluf_(p1.x + b0v), geluf_(p1.y + b1v));
                } else {
                    if (EPI == 2) {
                        float2 r0 = *reinterpret_cast<const float2*>(&res[(size_t)row0 * N + col]);
                        float2 r1 = *reinterpret_cast<const float2*>(&res[(size_t)row1 * N + col]);
                        p0.x += bias[col] + r0.x; p0.y += bias[col + 1] + r0.y;
                        p1.x += bias[col] + r1.x; p1.y += bias[col + 1] + r1.y;
                    } else if (EPI == 3) {
                        float2 r0 = *reinterpret_cast<const float2*>(&res[(size_t)row0 * N + col]);
                        float2 r1 = *reinterpret_cast<const float2*>(&res[(size_t)row1 * N + col]);
                        p0.x += r0.x; p0.y += r0.y;
                        p1.x += r1.x; p1.y += r1.y;
                    } else if (EPI == 4) {
                        if (col < DINNER) {
                            p0.x = siluf_(p0.x); p0.y = siluf_(p0.y);
                            p1.x = siluf_(p1.x); p1.y = siluf_(p1.y);
                        }
                    }
                    *reinterpret_cast<float2*>(&Cf[(size_t)row0 * N + col]) = p0;
                    *reinterpret_cast<float2*>(&Cf[(size_t)row1 * N + col]) = p1;
                }
            }
        }
    }
}

// ---------------- conv+silu -> fp16 v (gate untouched; silu'd in GEMM) -------
__global__ void conv_silu_kernel(const float* __restrict__ proj,
                                 const float* __restrict__ conv_w,
                                 __half* __restrict__ vh) {
    int idx = blockIdx.x * blockDim.x + threadIdx.x;
    if (idx >= BT * DINNER) return;
    int c  = idx % DINNER;
    int bt = idx / DINNER;
    int t  = bt % SEQ;
    float acc = 0.0f;
#pragma unroll
    for (int k = 0; k < DCONV; k++) {
        int tt = t - (DCONV - 1) + k;
        if (tt >= 0)
            acc = fmaf(proj[(size_t)(bt - (DCONV - 1) + k) * DPROJ + DINNER + c],
                       conv_w[c * DCONV + k], acc);
    }
    vh[idx] = __float2half(siluf_(acc));
}

// ---------------- sequential LinOSS-IM scan, 128 threads/block ---------------
// Thread layout: p = tid>>1 (D_HEAD lane), half = tid&1 (owns 4 of 8 states).
// bcparams FUSED into chunk staging: each (p,half) normalizes its own B/C half
// (partial sum + shfl_xor(1) to complete the norm); half==0 computes coef.
__global__ void scan_kernel(const float* __restrict__ bc,
                            const float* __restrict__ proj,   // gate silu'd; params raw f32
                            const __half* __restrict__ vh,
                            const float* __restrict__ Dsk,
                            __half* __restrict__ yh) {
    int bh = blockIdx.x;                  // 0..47
    int b = bh / NHEADS, h = bh % NHEADS;
    int tid  = threadIdx.x;               // 0..127
    int p    = tid >> 1;                   // 0..63
    int half = tid & 1;                    // state half
    float dskip = Dsk[h];

    __shared__ float4 shB[64 * 2];        // [t][half]
    __shared__ float4 shC[64 * 2];
    __shared__ float4 shCo[64];
    __shared__ float  shU[64 * 64];
    __shared__ float  shG[64 * 64];

    float z[4], xs[4];
#pragma unroll
    for (int n = 0; n < 4; n++) { z[n] = 0.0f; xs[n] = 0.0f; }

    for (int chunk = 0; chunk < SEQ / 64; chunk++) {
        __syncthreads();
        {
            // fused bcparams: normalize this thread's B/C half for time p
            int tB = chunk * 64 + p;
            size_t bcbase = (size_t)(b * SEQ + tB) * (2 * NHEADS * DSTATE) + h * 16;
            float4 bv = *reinterpret_cast<const float4*>(&bc[bcbase + half * 4]);
            float4 cv = *reinterpret_cast<const float4*>(&bc[bcbase + 8 + half * 4]);
            float ssb = fmaf(bv.x, bv.x, fmaf(bv.y, bv.y, fmaf(bv.z, bv.z, bv.w * bv.w)));
            float ssc = fmaf(cv.x, cv.x, fmaf(cv.y, cv.y, fmaf(cv.z, cv.z, cv.w * cv.w)));
            ssb += __shfl_xor_sync(0xffffffff, ssb, 1);
            ssc += __shfl_xor_sync(0xffffffff, ssc, 1);
            float rb = rsqrtf(ssb + 1e-12f);
            float rc = rsqrtf(ssc + 1e-12f);
            bv.x *= rb; bv.y *= rb; bv.z *= rb; bv.w *= rb;
            cv.x *= rc; cv.y *= rc; cv.z *= rc; cv.w *= rc;
            shB[p * 2 + half] = bv;
            shC[p * 2 + half] = cv;
            if (half == 0) {
                size_t pbase = (size_t)(b * SEQ + tB) * DPROJ + 2 * DINNER + h * 2;
                float p0 = proj[pbase], p1 = proj[pbase + 1];
                float Aq = softplusf_(p0);
                float dt = sigmoidf_(p1);
                float S  = 1.0f / (1.0f + dt * dt * Aq);
                shCo[p] = make_float4(S, S * dt * Aq, S * dt, dt);
            }
        }
        int base = b * SEQ + chunk * 64;
        // stage u (fp16 -> f32): 64 rows x 8 chunks = 512 jobs / 128 thr = 4 passes
#pragma unroll
        for (int pass = 0; pass < 4; pass++) {
            int idx = pass * 128 + tid;
            int row = idx >> 3, hc = idx & 7;
            uint4 hv = *reinterpret_cast<const uint4*>(
                &vh[(size_t)(base + row) * DINNER + h * DHEAD + hc * 8]);
            const __half2* hp = reinterpret_cast<const __half2*>(&hv);
            float* du = &shU[row * 64 + hc * 8];
#pragma unroll
            for (int j = 0; j < 4; j++) {
                float2 f = __half22float2(hp[j]);
                du[2 * j]     = f.x;
                du[2 * j + 1] = f.y;
            }
        }
        // stage gate (f32 float4): 64 rows x 16 chunks = 1024 jobs / 128 = 8 passes
#pragma unroll
        for (int pass = 0; pass < 8; pass++) {
            int idx = pass * 128 + tid;
            int row = idx >> 4, c4 = (idx & 15) << 2;
            float4 gg = *reinterpret_cast<const float4*>(
                &proj[(size_t)(base + row) * DPROJ + h * DHEAD + c4]);
            *reinterpret_cast<float4*>(&shG[row * 64 + c4]) = gg;
        }
        __syncthreads();

#pragma unroll 4
        for (int i = 0; i < 64; i++) {
            float4 co = shCo[i];
            float  u  = shU[i * 64 + p];
            float4 bv = shB[i * 2 + half];
            float4 cv = shC[i * 2 + half];
            float bb[4] = {bv.x, bv.y, bv.z, bv.w};
            float cc[4] = {cv.x, cv.y, cv.z, cv.w};
            float yv = 0.0f;
#pragma unroll
            for (int n = 0; n < 4; n++) {
                // z = S*z - (S*dt*A)*xs + (S*dt)*(B*u) ; xs += dt*z ; y += C*xs
                z[n]  = fmaf(co.x, z[n], fmaf(-co.y, xs[n], co.z * bb[n] * u));
                xs[n] = fmaf(co.w, z[n], xs[n]);
                yv    = fmaf(cc[n], xs[n], yv);
            }
            yv += __shfl_xor_sync(0xffffffff, yv, 1);
            if (half == 0) {
                float sg = shG[i * 64 + p];
                yh[(size_t)(base + i) * DINNER + h * DHEAD + p] =
                    __float2half((yv + dskip * u) * sg);
            }
        }
    }
}

// ---------------- launch ----------------
extern "C" void kernel_launch(void* const* d_in, const int* in_sizes, int n_in,
                              void* d_out, int out_size) {
    const float* x       = (const float*)d_in[0];
    const float* norm1_w = (const float*)d_in[1];
    const float* w_in    = (const float*)d_in[2];
    const float* conv_w  = (const float*)d_in[3];
    const float* w_bc    = (const float*)d_in[4];
    const float* D_skip  = (const float*)d_in[5];
    const float* w_out   = (const float*)d_in[6];
    const float* norm2_w = (const float*)d_in[7];
    const float* ff_w1   = (const float*)d_in[8];
    const float* ff_b1   = (const float*)d_in[9];
    const float* ff_w2   = (const float*)d_in[10];
    const float* ff_b2   = (const float*)d_in[11];
    float* out = (float*)d_out;

    float *proj, *bc, *x1;
    __half *xnh, *vh, *yh, *hh, *ffh, *wh;
    cudaGetSymbolAddress((void**)&proj, g_proj);
    cudaGetSymbolAddress((void**)&bc,   g_bc);
    cudaGetSymbolAddress((void**)&x1,   g_x1);
    cudaGetSymbolAddress((void**)&xnh,  g_xnh);
    cudaGetSymbolAddress((void**)&vh,   g_vh);
    cudaGetSymbolAddress((void**)&yh,   g_yh);
    cudaGetSymbolAddress((void**)&hh,   g_hh);
    cudaGetSymbolAddress((void**)&ffh,  g_ffh);
    cudaGetSymbolAddress((void**)&wh,   g_wh);

    // dynamic smem sizes (halves * 2 bytes), 3 stages
    const int SM128 = STAGES * (128 * ASTRH + 128 * ASTRH) * 2;  // 61440 B
    const int SM64  = STAGES * (128 * ASTRH + 64 * ASTRH)  * 2;  // 46080 B
    cudaFuncSetAttribute(gemm_fp16<128, 64, 32, 4>,
                         cudaFuncAttributeMaxDynamicSharedMemorySize, SM128);
    cudaFuncSetAttribute(gemm_fp16<128, 64, 32, 1>,
                         cudaFuncAttributeMaxDynamicSharedMemorySize, SM128);
    cudaFuncSetAttribute(gemm_fp16<64, 32, 32, 0>,
                         cudaFuncAttributeMaxDynamicSharedMemorySize, SM64);
    cudaFuncSetAttribute(gemm_fp16<64, 32, 32, 2>,
                         cudaFuncAttributeMaxDynamicSharedMemorySize, SM64);
    cudaFuncSetAttribute(gemm_fp16<64, 32, 32, 3>,
                         cudaFuncAttributeMaxDynamicSharedMemorySize, SM64);

    // 0. all weight transposes -> [N][K] fp16, single launch
    transpose_all_kernel<<<T5_END, dim3(32, 8)>>>(
        w_in, w_bc, w_out, ff_w1, ff_w2, wh);

    // 1. rmsnorm1 -> fp16
    rmsnorm_kernel<<<BT, 256>>>(x, norm1_w, xnh);
    // 2. proj = xn @ w_in (4096 x 3120 x 768), f32 out, gate pre-silu'd
    gemm_fp16<128, 64, 32, 4><<<dim3((DPROJ + 127) / 128, BT / 128), 256, SM128>>>(
        xnh, wh + W_IN_OFF, proj, BT, DPROJ, DMODEL, nullptr, nullptr);
    // 3. conv+silu -> fp16 v
    conv_silu_kernel<<<(BT * DINNER + 255) / 256, 256>>>(proj, conv_w, vh);
    // 4. bc = v @ w_bc (4096 x 384 x 1536), f32 out
    gemm_fp16<64, 32, 32, 0><<<dim3((2 * NHEADS * DSTATE) / 64, BT / 128), 256, SM64>>>(
        vh, wh + W_BC_OFF, bc, BT, 2 * NHEADS * DSTATE, DINNER, nullptr, nullptr);
    // 5. sequential scan (128 thr/block, bcparams fused) -> fp16 y
    scan_kernel<<<BATCH * NHEADS, 128>>>(bc, proj, vh, D_skip, yh);
    // 6. x1 = x + y @ w_out (4096 x 768 x 1536), f32 out  [BN=64: wave balance]
    gemm_fp16<64, 32, 32, 3><<<dim3(DMODEL / 64, BT / 128), 256, SM64>>>(
        yh, wh + W_OUT_OFF, x1, BT, DMODEL, DINNER, nullptr, x);
    // 7. rmsnorm2 -> fp16
    rmsnorm_kernel<<<BT, 256>>>(x1, norm2_w, hh);
    // 8. ff = gelu(h @ ff_w1 + b1) (4096 x 3072 x 768), fp16 out
    gemm_fp16<128, 64, 32, 1><<<dim3(DFF / 128, BT / 128), 256, SM128>>>(
        hh, wh + FF1_OFF, ffh, BT, DFF, DMODEL, ff_b1, nullptr);
    // 9. out = x1 + ff @ ff_w2 + b2 (4096 x 768 x 3072), f32 out [BN=64]
    gemm_fp16<64, 32, 32, 2><<<dim3(DMODEL / 64, BT / 128), 256, SM64>>>(
        ffh, wh + FF2_OFF, out, BT, DMODEL, DFF, ff_b2, x1);
}

// round 14
// speedup vs baseline: 1.0699x; 1.0699x over previous
#include <cuda_runtime.h>
#include <cuda_fp16.h>
#include <math.h>
#include <stdint.h>

// ---------------- problem constants ----------------
#define BATCH   2
#define SEQ     2048
#define BT      (BATCH*SEQ)      // 4096 rows
#define DMODEL  768
#define DINNER  1536
#define NHEADS  24
#define DHEAD   64
#define DSTATE  8
#define DCONV   4
#define DPROJ   3120             // 2*DINNER + NHEADS*2
#define DFF     3072

// transposed weight scratch offsets (halves); layout [N][K]
#define W_IN_OFF  0
#define W_BC_OFF  2396160                       // 768*3120
#define W_OUT_OFF 2985984                       // + 1536*384
#define FF1_OFF   4165632                       // + 1536*768
#define FF2_OFF   6524928                       // + 768*3072
#define W_TOTAL   8884224                       // + 3072*768

// merged-transpose tile ranges (32x32 tiles, Nt = tiles along N)
#define T1_END 2352      // w_in : 98*24
#define T2_END 2928      // w_bc : 12*48
#define T3_END 4080      // w_out: 24*48
#define T4_END 6384      // ff1  : 96*24
#define T5_END 8688      // ff2  : 24*96

// ---------------- scratch (static device globals; no allocation) ----------------
__device__ float  g_proj[BT*DPROJ];
__device__ float  g_bc  [BT*2*NHEADS*DSTATE];
__device__ float  g_Bn  [BT*NHEADS*DSTATE];
__device__ float  g_Cn  [BT*NHEADS*DSTATE];
__device__ float  g_coef[BT*NHEADS*4];
__device__ float  g_x1  [BT*DMODEL];
__device__ __half g_xnh [BT*DMODEL];
__device__ __half g_vh  [BT*DINNER];
__device__ __half g_yh  [BT*DINNER];
__device__ __half g_hh  [BT*DMODEL];
__device__ __half g_ffh [BT*DFF];
__device__ __half g_wh  [W_TOTAL];

// ---------------- device math helpers ----------------
__device__ __forceinline__ float sigmoidf_(float x) { return 1.0f / (1.0f + expf(-x)); }
__device__ __forceinline__ float siluf_(float x)    { return x * sigmoidf_(x); }
__device__ __forceinline__ float softplusf_(float x){ return fmaxf(x, 0.0f) + log1pf(expf(-fabsf(x))); }
__device__ __forceinline__ float geluf_(float x) {
    float x3 = x * x * x;
    float t  = tanhf(0.7978845608028654f * (x + 0.044715f * x3));
    return 0.5f * x * (1.0f + t);
}

// ---------------- merged transpose+convert: all 5 weights, one launch --------
__global__ void transpose_all_kernel(const float* __restrict__ w_in,
                                     const float* __restrict__ w_bc,
                                     const float* __restrict__ w_out,
                                     const float* __restrict__ ff1,
                                     const float* __restrict__ ff2,
                                     __half* __restrict__ wh) {
    __shared__ float tile[32][33];
    int id = blockIdx.x;
    const float* src; __half* dst; int K, N, Nt;
    if (id < T1_END)      {            src = w_in;  dst = wh + W_IN_OFF;  K = DMODEL; N = DPROJ; Nt = 98; }
    else if (id < T2_END) { id -= T1_END; src = w_bc;  dst = wh + W_BC_OFF;  K = DINNER; N = 384;   Nt = 12; }
    else if (id < T3_END) { id -= T2_END; src = w_out; dst = wh + W_OUT_OFF; K = DINNER; N = DMODEL;Nt = 24; }
    else if (id < T4_END) { id -= T3_END; src = ff1;   dst = wh + FF1_OFF;   K = DMODEL; N = DFF;   Nt = 96; }
    else                  { id -= T4_END; src = ff2;   dst = wh + FF2_OFF;   K = DFF;    N = DMODEL;Nt = 24; }
    int nb = (id % Nt) * 32, kb = (id / Nt) * 32;
    int tx = threadIdx.x, ty = threadIdx.y;   // 32 x 8
#pragma unroll
    for (int j = 0; j < 32; j += 8) {
        int k = kb + ty + j, n = nb + tx;
        tile[ty + j][tx] = (k < K && n < N) ? src[(size_t)k * N + n] : 0.0f;
    }
    __syncthreads();
#pragma unroll
    for (int j = 0; j < 32; j += 8) {
        int n = nb + ty + j, k = kb + tx;
        if (n < N && k < K) dst[(size_t)n * K + k] = __float2half(tile[tx][ty + j]);
    }
}

// ---------------- rmsnorm: one block per row, fp16 output ----------------
__global__ void rmsnorm_kernel(const float* __restrict__ x,
                               const float* __restrict__ w,
                               __half* __restrict__ out) {
    int row = blockIdx.x;
    const float* xr = x + (size_t)row * DMODEL;
    __half*    orow = out + (size_t)row * DMODEL;

    float xv[3];
    float ss = 0.0f;
#pragma unroll
    for (int j = 0; j < 3; j++) {
        int i = threadIdx.x + j * 256;
        float v = xr[i];
        xv[j] = v;
        ss += v * v;
    }
#pragma unroll
    for (int off = 16; off > 0; off >>= 1)
        ss += __shfl_xor_sync(0xffffffff, ss, off);
    __shared__ float sh[8];
    int lane = threadIdx.x & 31, wid = threadIdx.x >> 5;
    if (lane == 0) sh[wid] = ss;
    __syncthreads();
    if (wid == 0) {
        float v = (lane < 8) ? sh[lane] : 0.0f;
#pragma unroll
        for (int off = 4; off > 0; off >>= 1)
            v += __shfl_xor_sync(0xffffffff, v, off);
        if (lane == 0) sh[0] = rsqrtf(v * (1.0f / DMODEL) + 1e-6f);
    }
    __syncthreads();
    float s = sh[0];
#pragma unroll
    for (int j = 0; j < 3; j++) {
        int i = threadIdx.x + j * 256;
        orow[i] = __float2half(xv[j] * s * w[i]);
    }
}

// ============================================================================
// fp16 mma.sync GEMM (m16n8k16), 3-stage cp.async pipeline, dynamic smem.
//   C[M,N] = A[M,K] @ Bt[N,K]^T ; A,Bt fp16, accumulate fp32.
//   BM=128, BK=32, 256 threads (8 warps).
//   BN=128: warp grid 2x4, tile 64x32 | BN=64: warp grid 4x2, tile 32x32.
//   smem rows padded to 40 halves (80B) -> ldmatrix conflict-free.
//   EPI: 0 none(f32) | 1 half(gelu(acc+bias)) | 2 f32 acc+bias+res
//        | 3 f32 acc+res | 4 f32, silu applied when col < DINNER (proj gate)
// ============================================================================
#define ASTRH  40
#define STAGES 3

template <int BN, int WM, int WN, int EPI>
__global__ void __launch_bounds__(256)
gemm_fp16(const __half* __restrict__ A,
          const __half* __restrict__ Bt,
          void* __restrict__ Cv,
          int M, int N, int K,
          const float* __restrict__ bias,
          const float* __restrict__ res) {
    constexpr int MT   = WM / 16;
    constexpr int NT   = WN / 8;
    constexpr int WGM  = 128 / WM;
    constexpr int ASTG = 128 * ASTRH;
    constexpr int BSTG = BN * ASTRH;
    constexpr int BCH  = (BN * 4) / 256;

    extern __shared__ __half dsm[];
    __half* As = dsm;
    __half* Bs = dsm + STAGES * ASTG;

    const int tid  = threadIdx.x;
    const int warp = tid >> 5;
    const int lane = tid & 31;
    const int g    = lane >> 2;
    const int t    = lane & 3;
    const int sel  = lane >> 3;

    const int wm = (warp % WGM) * WM;
    const int wn = (warp / WGM) * WN;
    const int bm = blockIdx.y * 128;
    const int bn = blockIdx.x * BN;

    const int lrow  = wm + ((sel & 1) << 3) + (lane & 7);
    const int lcolh = (sel >> 1) << 3;
    const int brow  = ((sel >> 1) << 3) + (lane & 7);
    const int bcolh = (sel & 1) << 3;

    const uint32_t as0 = (uint32_t)__cvta_generic_to_shared(As);
    const uint32_t bs0 = (uint32_t)__cvta_generic_to_shared(Bs);

    float acc[MT][NT][4];
#pragma unroll
    for (int i = 0; i < MT; i++)
#pragma unroll
        for (int j = 0; j < NT; j++)
#pragma unroll
            for (int r = 0; r < 4; r++) acc[i][j][r] = 0.0f;

    const int nkt = K >> 5;

    auto issue = [&](int kt, int buf) {
        int k0 = kt << 5;
#pragma unroll
        for (int i = 0; i < 2; i++) {
            int idx = tid + (i << 8);
            int row = idx >> 2, c16 = idx & 3;
            const __half* src = &A[(size_t)(bm + row) * K + k0 + c16 * 8];
            uint32_t dst = as0 + (uint32_t)(buf * ASTG + row * ASTRH + c16 * 8) * 2u;
            asm volatile("cp.async.cg.shared.global [%0], [%1], 16;"
                         :: "r"(dst), "l"(src));
        }
#pragma unroll
        for (int i = 0; i < BCH; i++) {
            int idx = tid + (i << 8);
            int row = idx >> 2, c16 = idx & 3;
            int n = bn + row;
            const __half* src = &Bt[(size_t)(n < N ? n : 0) * K + k0 + c16 * 8];
            int sz = (n < N) ? 16 : 0;
            uint32_t dst = bs0 + (uint32_t)(buf * BSTG + row * ASTRH + c16 * 8) * 2u;
            asm volatile("cp.async.cg.shared.global [%0], [%1], 16, %2;"
                         :: "r"(dst), "l"(src), "r"(sz));
        }
        asm volatile("cp.async.commit_group;" ::: "memory");
    };

#pragma unroll
    for (int s = 0; s < STAGES - 1; ++s)
        if (s < nkt) issue(s, s);

    int buf = 0;
    for (int kt = 0; kt < nkt; ++kt) {
        asm volatile("cp.async.wait_group %0;" :: "n"(STAGES - 2) : "memory");
        __syncthreads();
        if (kt + STAGES - 1 < nkt)
            issue(kt + STAGES - 1, (kt + STAGES - 1) % STAGES);

#pragma unroll
        for (int ks = 0; ks < 2; ks++) {
            uint32_t a[MT][4];
#pragma unroll
            for (int mi = 0; mi < MT; mi++) {
                uint32_t addr = as0 + (uint32_t)(buf * ASTG +
                                (lrow + mi * 16) * ASTRH + ks * 16 + lcolh) * 2u;
                asm volatile(
                    "ldmatrix.sync.aligned.m8n8.x4.shared.b16 {%0,%1,%2,%3}, [%4];"
                    : "=r"(a[mi][0]), "=r"(a[mi][1]), "=r"(a[mi][2]), "=r"(a[mi][3])
                    : "r"(addr));
            }
            uint32_t b[NT][2];
#pragma unroll
            for (int nt2 = 0; nt2 < NT / 2; nt2++) {
                uint32_t addr = bs0 + (uint32_t)(buf * BSTG +
                                (wn + nt2 * 16 + brow) * ASTRH + ks * 16 + bcolh) * 2u;
                asm volatile(
                    "ldmatrix.sync.aligned.m8n8.x4.shared.b16 {%0,%1,%2,%3}, [%4];"
                    : "=r"(b[nt2 * 2][0]), "=r"(b[nt2 * 2][1]),
                      "=r"(b[nt2 * 2 + 1][0]), "=r"(b[nt2 * 2 + 1][1])
                    : "r"(addr));
            }
#pragma unroll
            for (int ni = 0; ni < NT; ni++)
#pragma unroll
                for (int mi = 0; mi < MT; mi++) {
                    asm volatile(
                        "mma.sync.aligned.m16n8k16.row.col.f32.f16.f16.f32 "
                        "{%0,%1,%2,%3},{%4,%5,%6,%7},{%8,%9},{%0,%1,%2,%3};"
                        : "+f"(acc[mi][ni][0]), "+f"(acc[mi][ni][1]),
                          "+f"(acc[mi][ni][2]), "+f"(acc[mi][ni][3])
                        : "r"(a[mi][0]), "r"(a[mi][1]), "r"(a[mi][2]), "r"(a[mi][3]),
                          "r"(b[ni][0]), "r"(b[ni][1]));
                }
        }
        buf = (buf + 1 == STAGES) ? 0 : buf + 1;
    }

    // ---- epilogue ----
    float*  Cf = (float*)Cv;
    __half* Ch = (__half*)Cv;
#pragma unroll
    for (int mi = 0; mi < MT; mi++) {
        int row0 = bm + wm + mi * 16 + g;
        int row1 = row0 + 8;
#pragma unroll
        for (int ni = 0; ni < NT; ni++) {
            int col = bn + wn + ni * 8 + 2 * t;
            if (col < N) {
                float2 p0 = make_float2(acc[mi][ni][0], acc[mi][ni][1]);
                float2 p1 = make_float2(acc[mi][ni][2], acc[mi][ni][3]);
                if (EPI == 1) {
                    float b0v = bias[col], b1v = bias[col + 1];
                    *reinterpret_cast<__half2*>(&Ch[(size_t)row0 * N + col]) =
                        __floats2half2_rn(geluf_(p0.x + b0v), geluf_(p0.y + b1v));
                    *reinterpret_cast<__half2*>(&Ch[(size_t)row1 * N + col]) =
                        __floats2half2_rn(geluf_(p1.x + b0v), geluf_(p1.y + b1v));
                } else {
                    if (EPI == 2) {
                        float2 r0 = *reinterpret_cast<const float2*>(&res[(size_t)row0 * N + col]);
                        float2 r1 = *reinterpret_cast<const float2*>(&res[(size_t)row1 * N + col]);
                        p0.x += bias[col] + r0.x; p0.y += bias[col + 1] + r0.y;
                        p1.x += bias[col] + r1.x; p1.y += bias[col + 1] + r1.y;
                    } else if (EPI == 3) {
                        float2 r0 = *reinterpret_cast<const float2*>(&res[(size_t)row0 * N + col]);
                        float2 r1 = *reinterpret_cast<const float2*>(&res[(size_t)row1 * N + col]);
                        p0.x += r0.x; p0.y += r0.y;
                        p1.x += r1.x; p1.y += r1.y;
                    } else if (EPI == 4) {
                        if (col < DINNER) {
                            p0.x = siluf_(p0.x); p0.y = siluf_(p0.y);
                            p1.x = siluf_(p1.x); p1.y = siluf_(p1.y);
                        }
                    }
                    *reinterpret_cast<float2*>(&Cf[(size_t)row0 * N + col]) = p0;
                    *reinterpret_cast<float2*>(&Cf[(size_t)row1 * N + col]) = p1;
                }
            }
        }
    }
}

// ---------------- smem-tiled conv+silu -> fp16 v ------------------------------
// Block = 64 timesteps x 64 channels. Stage 67x64 proj slab once; each output
// does 4 LDS+FMA. Chunks never straddle a batch boundary (SEQ % 64 == 0).
__global__ void __launch_bounds__(256)
conv_silu_kernel(const float* __restrict__ proj,
                 const float* __restrict__ conv_w,
                 __half* __restrict__ vh) {
    __shared__ float shP[67 * 64];
    __shared__ float shW[4][64];
    const int tid = threadIdx.x;          // 0..255
    const int bt0 = blockIdx.x * 64;
    const int c0  = blockIdx.y * 64;
    const bool seqstart = (bt0 % SEQ) == 0;

    {   // conv weights: 64 channels x 4 taps
        int c = tid >> 2, k = tid & 3;
        shW[k][c] = conv_w[(c0 + c) * DCONV + k];
    }
    // stage 67 rows x 16 float4 = 1072 jobs
#pragma unroll
    for (int pass = 0; pass < 5; pass++) {
        int idx = pass * 256 + tid;
        if (idx < 67 * 16) {
            int j = idx >> 4, q = idx & 15;
            float4 v = make_float4(0.f, 0.f, 0.f, 0.f);
            if (!(seqstart && j < 3))
                v = *reinterpret_cast<const float4*>(
                    &proj[(size_t)(bt0 - 3 + j) * DPROJ + DINNER + c0 + q * 4]);
            *reinterpret_cast<float4*>(&shP[j * 64 + q * 4]) = v;
        }
    }
    __syncthreads();
#pragma unroll
    for (int pass = 0; pass < 16; pass++) {
        int idx = pass * 256 + tid;
        int r = idx >> 6, c = idx & 63;
        float acc = 0.0f;
#pragma unroll
        for (int k = 0; k < 4; k++)
            acc = fmaf(shP[(r + k) * 64 + c], shW[k][c], acc);
        vh[(size_t)(bt0 + r) * DINNER + c0 + c] = __float2half(siluf_(acc));
    }
}

// ---------------- B/C normalize + scan coefficients ----------------
__global__ void bcparams_kernel(const float* __restrict__ bc,
                                const float* __restrict__ proj,
                                float* __restrict__ Bn,
                                float* __restrict__ Cn,
                                float* __restrict__ coef) {
    int idx = blockIdx.x * blockDim.x + threadIdx.x;
    if (idx >= BT * NHEADS) return;
    int h  = idx % NHEADS;
    int bt = idx / NHEADS;

    const float* p = bc + (size_t)bt * (2 * NHEADS * DSTATE) + h * 16;
    float bl[8], cl[8];
    float ssb = 0.0f, ssc = 0.0f;
#pragma unroll
    for (int n = 0; n < 8; n++) {
        bl[n] = p[n];     ssb = fmaf(bl[n], bl[n], ssb);
        cl[n] = p[8 + n]; ssc = fmaf(cl[n], cl[n], ssc);
    }
    float rb = rsqrtf(ssb + 1e-12f);
    float rc = rsqrtf(ssc + 1e-12f);
#pragma unroll
    for (int n = 0; n < 8; n++) {
        Bn[(size_t)idx * 8 + n] = bl[n] * rb;
        Cn[(size_t)idx * 8 + n] = cl[n] * rc;
    }
    float p0 = proj[(size_t)bt * DPROJ + 2 * DINNER + h * 2 + 0];
    float p1 = proj[(size_t)bt * DPROJ + 2 * DINNER + h * 2 + 1];
    float Aq = softplusf_(p0);
    float dt = sigmoidf_(p1);
    float S  = 1.0f / (1.0f + dt * dt * Aq);
    coef[(size_t)idx * 4 + 0] = S;
    coef[(size_t)idx * 4 + 1] = S * dt * Aq;
    coef[(size_t)idx * 4 + 2] = S * dt;
    coef[(size_t)idx * 4 + 3] = dt;
}

// ---------------- sequential LinOSS-IM scan, 128 threads/block ---------------
// Thread layout: p = tid>>1 (D_HEAD lane), half = tid&1 (owns 4 of 8 states).
// y reduction across the state halves via shfl_xor(1).
__global__ void scan_kernel(const float* __restrict__ Bn,
                            const float* __restrict__ Cn,
                            const float* __restrict__ coef,
                            const __half* __restrict__ vh,
                            const float* __restrict__ proj,   // gate already silu'd
                            const float* __restrict__ Dsk,
                            __half* __restrict__ yh) {
    int bh = blockIdx.x;                  // 0..47
    int b = bh / NHEADS, h = bh % NHEADS;
    int tid  = threadIdx.x;               // 0..127
    int p    = tid >> 1;                   // 0..63
    int half = tid & 1;                    // state half
    float dskip = Dsk[h];

    __shared__ float4 shB[64 * 2];        // [t][half]
    __shared__ float4 shC[64 * 2];
    __shared__ float4 shCo[64];
    __shared__ float  shU[64 * 64];
    __shared__ float  shG[64 * 64];

    float z[4], xs[4];
#pragma unroll
    for (int n = 0; n < 4; n++) { z[n] = 0.0f; xs[n] = 0.0f; }

    for (int chunk = 0; chunk < SEQ / 64; chunk++) {
        __syncthreads();
        {
            int tB  = chunk * 64 + p;
            int idx = (b * SEQ + tB) * NHEADS + h;
            shB[p * 2 + half] = *reinterpret_cast<const float4*>(&Bn[(size_t)idx * 8 + half * 4]);
            shC[p * 2 + half] = *reinterpret_cast<const float4*>(&Cn[(size_t)idx * 8 + half * 4]);
            if (half == 0)
                shCo[p] = *reinterpret_cast<const float4*>(&coef[(size_t)idx * 4]);
        }
        int base = b * SEQ + chunk * 64;
        // stage u (fp16 -> f32): 64 rows x 8 chunks = 512 jobs / 128 thr = 4 passes
#pragma unroll
        for (int pass = 0; pass < 4; pass++) {
            int idx = pass * 128 + tid;
            int row = idx >> 3, hc = idx & 7;
            uint4 hv = *reinterpret_cast<const uint4*>(
                &vh[(size_t)(base + row) * DINNER + h * DHEAD + hc * 8]);
            const __half2* hp = reinterpret_cast<const __half2*>(&hv);
            float* du = &shU[row * 64 + hc * 8];
#pragma unroll
            for (int j = 0; j < 4; j++) {
                float2 f = __half22float2(hp[j]);
                du[2 * j]     = f.x;
                du[2 * j + 1] = f.y;
            }
        }
        // stage gate (f32 float4): 64 rows x 16 chunks = 1024 jobs / 128 = 8 passes
#pragma unroll
        for (int pass = 0; pass < 8; pass++) {
            int idx = pass * 128 + tid;
            int row = idx >> 4, c4 = (idx & 15) << 2;
            float4 gg = *reinterpret_cast<const float4*>(
                &proj[(size_t)(base + row) * DPROJ + h * DHEAD + c4]);
            *reinterpret_cast<float4*>(&shG[row * 64 + c4]) = gg;
        }
        __syncthreads();

#pragma unroll 4
        for (int i = 0; i < 64; i++) {
            float4 co = shCo[i];
            float  u  = shU[i * 64 + p];
            float4 bv = shB[i * 2 + half];
            float4 cv = shC[i * 2 + half];
            float bb[4] = {bv.x, bv.y, bv.z, bv.w};
            float cc[4] = {cv.x, cv.y, cv.z, cv.w};
            float yv = 0.0f;
#pragma unroll
            for (int n = 0; n < 4; n++) {
                z[n]  = fmaf(co.x, z[n], fmaf(-co.y, xs[n], co.z * bb[n] * u));
                xs[n] = fmaf(co.w, z[n], xs[n]);
                yv    = fmaf(cc[n], xs[n], yv);
            }
            yv += __shfl_xor_sync(0xffffffff, yv, 1);
            if (half == 0) {
                float sg = shG[i * 64 + p];
                yh[(size_t)(base + i) * DINNER + h * DHEAD + p] =
                    __float2half((yv + dskip * u) * sg);
            }
        }
    }
}

// ---------------- launch ----------------
extern "C" void kernel_launch(void* const* d_in, const int* in_sizes, int n_in,
                              void* d_out, int out_size) {
    const float* x       = (const float*)d_in[0];
    const float* norm1_w = (const float*)d_in[1];
    const float* w_in    = (const float*)d_in[2];
    const float* conv_w  = (const float*)d_in[3];
    const float* w_bc    = (const float*)d_in[4];
    const float* D_skip  = (const float*)d_in[5];
    const float* w_out   = (const float*)d_in[6];
    const float* norm2_w = (const float*)d_in[7];
    const float* ff_w1   = (const float*)d_in[8];
    const float* ff_b1   = (const float*)d_in[9];
    const float* ff_w2   = (const float*)d_in[10];
    const float* ff_b2   = (const float*)d_in[11];
    float* out = (float*)d_out;

    float *proj, *bc, *Bn, *Cn, *coef, *x1;
    __half *xnh, *vh, *yh, *hh, *ffh, *wh;
    cudaGetSymbolAddress((void**)&proj, g_proj);
    cudaGetSymbolAddress((void**)&bc,   g_bc);
    cudaGetSymbolAddress((void**)&Bn,   g_Bn);
    cudaGetSymbolAddress((void**)&Cn,   g_Cn);
    cudaGetSymbolAddress((void**)&coef, g_coef);
    cudaGetSymbolAddress((void**)&x1,   g_x1);
    cudaGetSymbolAddress((void**)&xnh,  g_xnh);
    cudaGetSymbolAddress((void**)&vh,   g_vh);
    cudaGetSymbolAddress((void**)&yh,   g_yh);
    cudaGetSymbolAddress((void**)&hh,   g_hh);
    cudaGetSymbolAddress((void**)&ffh,  g_ffh);
    cudaGetSymbolAddress((void**)&wh,   g_wh);

    // dynamic smem sizes (halves * 2 bytes), 3 stages
    const int SM128 = STAGES * (128 * ASTRH + 128 * ASTRH) * 2;  // 61440 B
    const int SM64  = STAGES * (128 * ASTRH + 64 * ASTRH)  * 2;  // 46080 B
    cudaFuncSetAttribute(gemm_fp16<128, 64, 32, 4>,
                         cudaFuncAttributeMaxDynamicSharedMemorySize, SM128);
    cudaFuncSetAttribute(gemm_fp16<128, 64, 32, 1>,
                         cudaFuncAttributeMaxDynamicSharedMemorySize, SM128);
    cudaFuncSetAttribute(gemm_fp16<64, 32, 32, 0>,
                         cudaFuncAttributeMaxDynamicSharedMemorySize, SM64);
    cudaFuncSetAttribute(gemm_fp16<64, 32, 32, 2>,
                         cudaFuncAttributeMaxDynamicSharedMemorySize, SM64);
    cudaFuncSetAttribute(gemm_fp16<64, 32, 32, 3>,
                         cudaFuncAttributeMaxDynamicSharedMemorySize, SM64);

    // 0. all weight transposes -> [N][K] fp16, single launch
    transpose_all_kernel<<<T5_END, dim3(32, 8)>>>(
        w_in, w_bc, w_out, ff_w1, ff_w2, wh);

    // 1. rmsnorm1 -> fp16
    rmsnorm_kernel<<<BT, 256>>>(x, norm1_w, xnh);
    // 2. proj = xn @ w_in (4096 x 3120 x 768), f32 out, gate pre-silu'd
    gemm_fp16<128, 64, 32, 4><<<dim3((DPROJ + 127) / 128, BT / 128), 256, SM128>>>(
        xnh, wh + W_IN_OFF, proj, BT, DPROJ, DMODEL, nullptr, nullptr);
    // 3. smem-tiled conv+silu -> fp16 v
    conv_silu_kernel<<<dim3(BT / 64, DINNER / 64), 256>>>(proj, conv_w, vh);
    // 4. bc = v @ w_bc (4096 x 384 x 1536), f32 out
    gemm_fp16<64, 32, 32, 0><<<dim3((2 * NHEADS * DSTATE) / 64, BT / 128), 256, SM64>>>(
        vh, wh + W_BC_OFF, bc, BT, 2 * NHEADS * DSTATE, DINNER, nullptr, nullptr);
    // 5. normalize B/C + scan coefficients
    bcparams_kernel<<<(BT * NHEADS + 127) / 128, 128>>>(bc, proj, Bn, Cn, coef);
    // 6. sequential scan (128 thr/block, 2 states/thread), gate+skip fused -> fp16 y
    scan_kernel<<<BATCH * NHEADS, 128>>>(Bn, Cn, coef, vh, proj, D_skip, yh);
    // 7. x1 = x + y @ w_out (4096 x 768 x 1536), f32 out  [BN=64: wave balance]
    gemm_fp16<64, 32, 32, 3><<<dim3(DMODEL / 64, BT / 128), 256, SM64>>>(
        yh, wh + W_OUT_OFF, x1, BT, DMODEL, DINNER, nullptr, x);
    // 8. rmsnorm2 -> fp16
    rmsnorm_kernel<<<BT, 256>>>(x1, norm2_w, hh);
    // 9. ff = gelu(h @ ff_w1 + b1) (4096 x 3072 x 768), fp16 out
    gemm_fp16<128, 64, 32, 1><<<dim3(DFF / 128, BT / 128), 256, SM128>>>(
        hh, wh + FF1_OFF, ffh, BT, DFF, DMODEL, ff_b1, nullptr);
    // 10. out = x1 + ff @ ff_w2 + b2 (4096 x 768 x 3072), f32 out [BN=64]
    gemm_fp16<64, 32, 32, 2><<<dim3(DMODEL / 64, BT / 128), 256, SM64>>>(
        ffh, wh + FF2_OFF, out, BT, DMODEL, DFF, ff_b2, x1);
}

// round 15
// speedup vs baseline: 1.0941x; 1.0226x over previous
#include <cuda_runtime.h>
#include <cuda_fp16.h>
#include <math.h>
#include <stdint.h>

// ---------------- problem constants ----------------
#define BATCH   2
#define SEQ     2048
#define BT      (BATCH*SEQ)      // 4096 rows
#define DMODEL  768
#define DINNER  1536
#define NHEADS  24
#define DHEAD   64
#define DSTATE  8
#define DCONV   4
#define DPROJ   3120             // 2*DINNER + NHEADS*2
#define DGV     3072             // gate+vraw fp16 region width
#define NPAR    48               // params columns (f32 side buffer)
#define DFF     3072

// transposed weight scratch offsets (halves); layout [N][K]
#define W_IN_OFF  0
#define W_BC_OFF  2396160                       // 768*3120
#define W_OUT_OFF 2985984                       // + 1536*384
#define FF1_OFF   4165632                       // + 1536*768
#define FF2_OFF   6524928                       // + 768*3072
#define W_TOTAL   8884224                       // + 3072*768

// merged-transpose tile ranges (32x32 tiles, Nt = tiles along N)
#define T1_END 2352      // w_in : 98*24
#define T2_END 2928      // w_bc : 12*48
#define T3_END 4080      // w_out: 24*48
#define T4_END 6384      // ff1  : 96*24
#define T5_END 8688      // ff2  : 24*96

// ---------------- scratch (static device globals; no allocation) ----------------
__device__ float  g_bc  [BT*2*NHEADS*DSTATE];
__device__ float  g_Bn  [BT*NHEADS*DSTATE];
__device__ float  g_Cn  [BT*NHEADS*DSTATE];
__device__ float  g_coef[BT*NHEADS*4];
__device__ float  g_par [BT*NPAR];
__device__ float  g_x1  [BT*DMODEL];
__device__ __half g_projh[BT*DGV];            // silu(gate) | vraw (fp16)
__device__ __half g_xnh [BT*DMODEL];
__device__ __half g_vh  [BT*DINNER];
__device__ __half g_yh  [BT*DINNER];
__device__ __half g_hh  [BT*DMODEL];
__device__ __half g_ffh [BT*DFF];
__device__ __half g_wh  [W_TOTAL];

// ---------------- device math helpers ----------------
__device__ __forceinline__ float sigmoidf_(float x) { return 1.0f / (1.0f + expf(-x)); }
__device__ __forceinline__ float siluf_(float x)    { return x * sigmoidf_(x); }
__device__ __forceinline__ float softplusf_(float x){ return fmaxf(x, 0.0f) + log1pf(expf(-fabsf(x))); }
__device__ __forceinline__ float geluf_(float x) {
    float x3 = x * x * x;
    float t  = tanhf(0.7978845608028654f * (x + 0.044715f * x3));
    return 0.5f * x * (1.0f + t);
}

// ---------------- merged transpose+convert: all 5 weights, one launch --------
__global__ void transpose_all_kernel(const float* __restrict__ w_in,
                                     const float* __restrict__ w_bc,
                                     const float* __restrict__ w_out,
                                     const float* __restrict__ ff1,
                                     const float* __restrict__ ff2,
                                     __half* __restrict__ wh) {
    __shared__ float tile[32][33];
    int id = blockIdx.x;
    const float* src; __half* dst; int K, N, Nt;
    if (id < T1_END)      {            src = w_in;  dst = wh + W_IN_OFF;  K = DMODEL; N = DPROJ; Nt = 98; }
    else if (id < T2_END) { id -= T1_END; src = w_bc;  dst = wh + W_BC_OFF;  K = DINNER; N = 384;   Nt = 12; }
    else if (id < T3_END) { id -= T2_END; src = w_out; dst = wh + W_OUT_OFF; K = DINNER; N = DMODEL;Nt = 24; }
    else if (id < T4_END) { id -= T3_END; src = ff1;   dst = wh + FF1_OFF;   K = DMODEL; N = DFF;   Nt = 96; }
    else                  { id -= T4_END; src = ff2;   dst = wh + FF2_OFF;   K = DFF;    N = DMODEL;Nt = 24; }
    int nb = (id % Nt) * 32, kb = (id / Nt) * 32;
    int tx = threadIdx.x, ty = threadIdx.y;   // 32 x 8
#pragma unroll
    for (int j = 0; j < 32; j += 8) {
        int k = kb + ty + j, n = nb + tx;
        tile[ty + j][tx] = (k < K && n < N) ? src[(size_t)k * N + n] : 0.0f;
    }
    __syncthreads();
#pragma unroll
    for (int j = 0; j < 32; j += 8) {
        int n = nb + ty + j, k = kb + tx;
        if (n < N && k < K) dst[(size_t)n * K + k] = __float2half(tile[tx][ty + j]);
    }
}

// ---------------- rmsnorm: one block per row, fp16 output ----------------
__global__ void rmsnorm_kernel(const float* __restrict__ x,
                               const float* __restrict__ w,
                               __half* __restrict__ out) {
    int row = blockIdx.x;
    const float* xr = x + (size_t)row * DMODEL;
    __half*    orow = out + (size_t)row * DMODEL;

    float xv[3];
    float ss = 0.0f;
#pragma unroll
    for (int j = 0; j < 3; j++) {
        int i = threadIdx.x + j * 256;
        float v = xr[i];
        xv[j] = v;
        ss += v * v;
    }
#pragma unroll
    for (int off = 16; off > 0; off >>= 1)
        ss += __shfl_xor_sync(0xffffffff, ss, off);
    __shared__ float sh[8];
    int lane = threadIdx.x & 31, wid = threadIdx.x >> 5;
    if (lane == 0) sh[wid] = ss;
    __syncthreads();
    if (wid == 0) {
        float v = (lane < 8) ? sh[lane] : 0.0f;
#pragma unroll
        for (int off = 4; off > 0; off >>= 1)
            v += __shfl_xor_sync(0xffffffff, v, off);
        if (lane == 0) sh[0] = rsqrtf(v * (1.0f / DMODEL) + 1e-6f);
    }
    __syncthreads();
    float s = sh[0];
#pragma unroll
    for (int j = 0; j < 3; j++) {
        int i = threadIdx.x + j * 256;
        orow[i] = __float2half(xv[j] * s * w[i]);
    }
}

// ============================================================================
// fp16 mma.sync GEMM (m16n8k16), 3-stage cp.async pipeline, dynamic smem.
//   C[M,N] = A[M,K] @ Bt[N,K]^T ; A,Bt fp16, accumulate fp32.
//   BM=128, BK=32, 256 threads (8 warps).
//   EPI: 0 none(f32) | 1 half(gelu(acc+bias)) | 2 f32 acc+bias+res
//        | 3 f32 acc+res
//        | 5 proj split: col<DINNER -> silu->fp16, col<DGV -> fp16 (stride DGV),
//                        col>=DGV -> f32 aux[row*NPAR + col-DGV]
// ============================================================================
#define ASTRH  40
#define STAGES 3

template <int BN, int WM, int WN, int EPI>
__global__ void __launch_bounds__(256)
gemm_fp16(const __half* __restrict__ A,
          const __half* __restrict__ Bt,
          void* __restrict__ Cv,
          int M, int N, int K,
          const float* __restrict__ bias,
          const float* __restrict__ res,
          float* __restrict__ aux) {
    constexpr int MT   = WM / 16;
    constexpr int NT   = WN / 8;
    constexpr int WGM  = 128 / WM;
    constexpr int ASTG = 128 * ASTRH;
    constexpr int BSTG = BN * ASTRH;
    constexpr int BCH  = (BN * 4) / 256;

    extern __shared__ __half dsm[];
    __half* As = dsm;
    __half* Bs = dsm + STAGES * ASTG;

    const int tid  = threadIdx.x;
    const int warp = tid >> 5;
    const int lane = tid & 31;
    const int g    = lane >> 2;
    const int t    = lane & 3;
    const int sel  = lane >> 3;

    const int wm = (warp % WGM) * WM;
    const int wn = (warp / WGM) * WN;
    const int bm = blockIdx.y * 128;
    const int bn = blockIdx.x * BN;

    const int lrow  = wm + ((sel & 1) << 3) + (lane & 7);
    const int lcolh = (sel >> 1) << 3;
    const int brow  = ((sel >> 1) << 3) + (lane & 7);
    const int bcolh = (sel & 1) << 3;

    const uint32_t as0 = (uint32_t)__cvta_generic_to_shared(As);
    const uint32_t bs0 = (uint32_t)__cvta_generic_to_shared(Bs);

    float acc[MT][NT][4];
#pragma unroll
    for (int i = 0; i < MT; i++)
#pragma unroll
        for (int j = 0; j < NT; j++)
#pragma unroll
            for (int r = 0; r < 4; r++) acc[i][j][r] = 0.0f;

    const int nkt = K >> 5;

    auto issue = [&](int kt, int buf) {
        int k0 = kt << 5;
#pragma unroll
        for (int i = 0; i < 2; i++) {
            int idx = tid + (i << 8);
            int row = idx >> 2, c16 = idx & 3;
            const __half* src = &A[(size_t)(bm + row) * K + k0 + c16 * 8];
            uint32_t dst = as0 + (uint32_t)(buf * ASTG + row * ASTRH + c16 * 8) * 2u;
            asm volatile("cp.async.cg.shared.global [%0], [%1], 16;"
                         :: "r"(dst), "l"(src));
        }
#pragma unroll
        for (int i = 0; i < BCH; i++) {
            int idx = tid + (i << 8);
            int row = idx >> 2, c16 = idx & 3;
            int n = bn + row;
            const __half* src = &Bt[(size_t)(n < N ? n : 0) * K + k0 + c16 * 8];
            int sz = (n < N) ? 16 : 0;
            uint32_t dst = bs0 + (uint32_t)(buf * BSTG + row * ASTRH + c16 * 8) * 2u;
            asm volatile("cp.async.cg.shared.global [%0], [%1], 16, %2;"
                         :: "r"(dst), "l"(src), "r"(sz));
        }
        asm volatile("cp.async.commit_group;" ::: "memory");
    };

#pragma unroll
    for (int s = 0; s < STAGES - 1; ++s)
        if (s < nkt) issue(s, s);

    int buf = 0;
    for (int kt = 0; kt < nkt; ++kt) {
        asm volatile("cp.async.wait_group %0;" :: "n"(STAGES - 2) : "memory");
        __syncthreads();
        if (kt + STAGES - 1 < nkt)
            issue(kt + STAGES - 1, (kt + STAGES - 1) % STAGES);

#pragma unroll
        for (int ks = 0; ks < 2; ks++) {
            uint32_t a[MT][4];
#pragma unroll
            for (int mi = 0; mi < MT; mi++) {
                uint32_t addr = as0 + (uint32_t)(buf * ASTG +
                                (lrow + mi * 16) * ASTRH + ks * 16 + lcolh) * 2u;
                asm volatile(
                    "ldmatrix.sync.aligned.m8n8.x4.shared.b16 {%0,%1,%2,%3}, [%4];"
                    : "=r"(a[mi][0]), "=r"(a[mi][1]), "=r"(a[mi][2]), "=r"(a[mi][3])
                    : "r"(addr));
            }
            uint32_t b[NT][2];
#pragma unroll
            for (int nt2 = 0; nt2 < NT / 2; nt2++) {
                uint32_t addr = bs0 + (uint32_t)(buf * BSTG +
                                (wn + nt2 * 16 + brow) * ASTRH + ks * 16 + bcolh) * 2u;
                asm volatile(
                    "ldmatrix.sync.aligned.m8n8.x4.shared.b16 {%0,%1,%2,%3}, [%4];"
                    : "=r"(b[nt2 * 2][0]), "=r"(b[nt2 * 2][1]),
                      "=r"(b[nt2 * 2 + 1][0]), "=r"(b[nt2 * 2 + 1][1])
                    : "r"(addr));
            }
#pragma unroll
            for (int ni = 0; ni < NT; ni++)
#pragma unroll
                for (int mi = 0; mi < MT; mi++) {
                    asm volatile(
                        "mma.sync.aligned.m16n8k16.row.col.f32.f16.f16.f32 "
                        "{%0,%1,%2,%3},{%4,%5,%6,%7},{%8,%9},{%0,%1,%2,%3};"
                        : "+f"(acc[mi][ni][0]), "+f"(acc[mi][ni][1]),
                          "+f"(acc[mi][ni][2]), "+f"(acc[mi][ni][3])
                        : "r"(a[mi][0]), "r"(a[mi][1]), "r"(a[mi][2]), "r"(a[mi][3]),
                          "r"(b[ni][0]), "r"(b[ni][1]));
                }
        }
        buf = (buf + 1 == STAGES) ? 0 : buf + 1;
    }

    // ---- epilogue ----
    float*  Cf = (float*)Cv;
    __half* Ch = (__half*)Cv;
#pragma unroll
    for (int mi = 0; mi < MT; mi++) {
        int row0 = bm + wm + mi * 16 + g;
        int row1 = row0 + 8;
#pragma unroll
        for (int ni = 0; ni < NT; ni++) {
            int col = bn + wn + ni * 8 + 2 * t;
            if (col < N) {
                float2 p0 = make_float2(acc[mi][ni][0], acc[mi][ni][1]);
                float2 p1 = make_float2(acc[mi][ni][2], acc[mi][ni][3]);
                if (EPI == 1) {
                    float b0v = bias[col], b1v = bias[col + 1];
                    *reinterpret_cast<__half2*>(&Ch[(size_t)row0 * N + col]) =
                        __floats2half2_rn(geluf_(p0.x + b0v), geluf_(p0.y + b1v));
                    *reinterpret_cast<__half2*>(&Ch[(size_t)row1 * N + col]) =
                        __floats2half2_rn(geluf_(p1.x + b0v), geluf_(p1.y + b1v));
                } else if (EPI == 5) {
                    if (col < DGV) {
                        if (col < DINNER) {
                            p0.x = siluf_(p0.x); p0.y = siluf_(p0.y);
                            p1.x = siluf_(p1.x); p1.y = siluf_(p1.y);
                        }
                        *reinterpret_cast<__half2*>(&Ch[(size_t)row0 * DGV + col]) =
                            __floats2half2_rn(p0.x, p0.y);
                        *reinterpret_cast<__half2*>(&Ch[(size_t)row1 * DGV + col]) =
                            __floats2half2_rn(p1.x, p1.y);
                    } else {
                        int pc = col - DGV;
                        *reinterpret_cast<float2*>(&aux[(size_t)row0 * NPAR + pc]) = p0;
                        *reinterpret_cast<float2*>(&aux[(size_t)row1 * NPAR + pc]) = p1;
                    }
                } else {
                    if (EPI == 2) {
                        float2 r0 = *reinterpret_cast<const float2*>(&res[(size_t)row0 * N + col]);
                        float2 r1 = *reinterpret_cast<const float2*>(&res[(size_t)row1 * N + col]);
                        p0.x += bias[col] + r0.x; p0.y += bias[col + 1] + r0.y;
                        p1.x += bias[col] + r1.x; p1.y += bias[col + 1] + r1.y;
                    } else if (EPI == 3) {
                        float2 r0 = *reinterpret_cast<const float2*>(&res[(size_t)row0 * N + col]);
                        float2 r1 = *reinterpret_cast<const float2*>(&res[(size_t)row1 * N + col]);
                        p0.x += r0.x; p0.y += r0.y;
                        p1.x += r1.x; p1.y += r1.y;
                    }
                    *reinterpret_cast<float2*>(&Cf[(size_t)row0 * N + col]) = p0;
                    *reinterpret_cast<float2*>(&Cf[(size_t)row1 * N + col]) = p1;
                }
            }
        }
    }
}

// ---------------- smem-tiled conv+silu -> fp16 v (fp16 vraw input) -----------
// Block = 64 timesteps x 64 channels; 67x64 slab staged once.
__global__ void __launch_bounds__(256)
conv_silu_kernel(const __half* __restrict__ projh,
                 const float* __restrict__ conv_w,
                 __half* __restrict__ vh) {
    __shared__ float shP[67 * 64];
    __shared__ float shW[4][64];
    const int tid = threadIdx.x;          // 0..255
    const int bt0 = blockIdx.x * 64;
    const int c0  = blockIdx.y * 64;
    const bool seqstart = (bt0 % SEQ) == 0;

    {   // conv weights: 64 channels x 4 taps
        int c = tid >> 2, k = tid & 3;
        shW[k][c] = conv_w[(c0 + c) * DCONV + k];
    }
    // stage 67 rows x 8 fp16-chunks(16B = 8 halves) = 536 jobs
#pragma unroll
    for (int pass = 0; pass < 3; pass++) {
        int idx = pass * 256 + tid;
        if (idx < 67 * 8) {
            int j = idx >> 3, hc = idx & 7;
            uint4 hv = make_uint4(0u, 0u, 0u, 0u);
            if (!(seqstart && j < 3))
                hv = *reinterpret_cast<const uint4*>(
                    &projh[(size_t)(bt0 - 3 + j) * DGV + DINNER + c0 + hc * 8]);
            const __half2* hp = reinterpret_cast<const __half2*>(&hv);
            float* dp = &shP[j * 64 + hc * 8];
#pragma unroll
            for (int q = 0; q < 4; q++) {
                float2 f = __half22float2(hp[q]);
                dp[2 * q]     = f.x;
                dp[2 * q + 1] = f.y;
            }
        }
    }
    __syncthreads();
#pragma unroll
    for (int pass = 0; pass < 16; pass++) {
        int idx = pass * 256 + tid;
        int r = idx >> 6, c = idx & 63;
        float acc = 0.0f;
#pragma unroll
        for (int k = 0; k < 4; k++)
            acc = fmaf(shP[(r + k) * 64 + c], shW[k][c], acc);
        vh[(size_t)(bt0 + r) * DINNER + c0 + c] = __float2half(siluf_(acc));
    }
}

// ---------------- B/C normalize + scan coefficients (f32 params) -------------
__global__ void bcparams_kernel(const float* __restrict__ bc,
                                const float* __restrict__ par,
                                float* __restrict__ Bn,
                                float* __restrict__ Cn,
                                float* __restrict__ coef) {
    int idx = blockIdx.x * blockDim.x + threadIdx.x;
    if (idx >= BT * NHEADS) return;
    int h  = idx % NHEADS;
    int bt = idx / NHEADS;

    const float* p = bc + (size_t)bt * (2 * NHEADS * DSTATE) + h * 16;
    float bl[8], cl[8];
    float ssb = 0.0f, ssc = 0.0f;
#pragma unroll
    for (int n = 0; n < 8; n++) {
        bl[n] = p[n];     ssb = fmaf(bl[n], bl[n], ssb);
        cl[n] = p[8 + n]; ssc = fmaf(cl[n], cl[n], ssc);
    }
    float rb = rsqrtf(ssb + 1e-12f);
    float rc = rsqrtf(ssc + 1e-12f);
#pragma unroll
    for (int n = 0; n < 8; n++) {
        Bn[(size_t)idx * 8 + n] = bl[n] * rb;
        Cn[(size_t)idx * 8 + n] = cl[n] * rc;
    }
    float p0 = par[(size_t)bt * NPAR + h * 2 + 0];
    float p1 = par[(size_t)bt * NPAR + h * 2 + 1];
    float Aq = softplusf_(p0);
    float dt = sigmoidf_(p1);
    float S  = 1.0f / (1.0f + dt * dt * Aq);
    coef[(size_t)idx * 4 + 0] = S;
    coef[(size_t)idx * 4 + 1] = S * dt * Aq;
    coef[(size_t)idx * 4 + 2] = S * dt;
    coef[(size_t)idx * 4 + 3] = dt;
}

// ---------------- sequential LinOSS-IM scan, 128 threads/block ---------------
// p = tid>>1 (D_HEAD lane), half = tid&1 (4 of 8 states); y via shfl_xor(1).
__global__ void scan_kernel(const float* __restrict__ Bn,
                            const float* __restrict__ Cn,
                            const float* __restrict__ coef,
                            const __half* __restrict__ vh,
                            const __half* __restrict__ projh,  // gate silu'd fp16
                            const float* __restrict__ Dsk,
                            __half* __restrict__ yh) {
    int bh = blockIdx.x;                  // 0..47
    int b = bh / NHEADS, h = bh % NHEADS;
    int tid  = threadIdx.x;               // 0..127
    int p    = tid >> 1;                   // 0..63
    int half = tid & 1;                    // state half
    float dskip = Dsk[h];

    __shared__ float4 shB[64 * 2];
    __shared__ float4 shC[64 * 2];
    __shared__ float4 shCo[64];
    __shared__ float  shU[64 * 64];
    __shared__ float  shG[64 * 64];

    float z[4], xs[4];
#pragma unroll
    for (int n = 0; n < 4; n++) { z[n] = 0.0f; xs[n] = 0.0f; }

    for (int chunk = 0; chunk < SEQ / 64; chunk++) {
        __syncthreads();
        {
            int tB  = chunk * 64 + p;
            int idx = (b * SEQ + tB) * NHEADS + h;
            shB[p * 2 + half] = *reinterpret_cast<const float4*>(&Bn[(size_t)idx * 8 + half * 4]);
            shC[p * 2 + half] = *reinterpret_cast<const float4*>(&Cn[(size_t)idx * 8 + half * 4]);
            if (half == 0)
                shCo[p] = *reinterpret_cast<const float4*>(&coef[(size_t)idx * 4]);
        }
        int base = b * SEQ + chunk * 64;
        // stage u (fp16 -> f32): 64 rows x 8 chunks = 512 jobs / 128 thr = 4 passes
#pragma unroll
        for (int pass = 0; pass < 4; pass++) {
            int idx = pass * 128 + tid;
            int row = idx >> 3, hc = idx & 7;
            uint4 hv = *reinterpret_cast<const uint4*>(
                &vh[(size_t)(base + row) * DINNER + h * DHEAD + hc * 8]);
            const __half2* hp = reinterpret_cast<const __half2*>(&hv);
            float* du = &shU[row * 64 + hc * 8];
#pragma unroll
            for (int j = 0; j < 4; j++) {
                float2 f = __half22float2(hp[j]);
                du[2 * j]     = f.x;
                du[2 * j + 1] = f.y;
            }
        }
        // stage gate (fp16 -> f32): same shape, from projh
#pragma unroll
        for (int pass = 0; pass < 4; pass++) {
            int idx = pass * 128 + tid;
            int row = idx >> 3, hc = idx & 7;
            uint4 hv = *reinterpret_cast<const uint4*>(
                &projh[(size_t)(base + row) * DGV + h * DHEAD + hc * 8]);
            const __half2* hp = reinterpret_cast<const __half2*>(&hv);
            float* dg = &shG[row * 64 + hc * 8];
#pragma unroll
            for (int j = 0; j < 4; j++) {
                float2 f = __half22float2(hp[j]);
                dg[2 * j]     = f.x;
                dg[2 * j + 1] = f.y;
            }
        }
        __syncthreads();

#pragma unroll 4
        for (int i = 0; i < 64; i++) {
            float4 co = shCo[i];
            float  u  = shU[i * 64 + p];
            float4 bv = shB[i * 2 + half];
            float4 cv = shC[i * 2 + half];
            float bb[4] = {bv.x, bv.y, bv.z, bv.w};
            float cc[4] = {cv.x, cv.y, cv.z, cv.w};
            float yv = 0.0f;
#pragma unroll
            for (int n = 0; n < 4; n++) {
                z[n]  = fmaf(co.x, z[n], fmaf(-co.y, xs[n], co.z * bb[n] * u));
                xs[n] = fmaf(co.w, z[n], xs[n]);
                yv    = fmaf(cc[n], xs[n], yv);
            }
            yv += __shfl_xor_sync(0xffffffff, yv, 1);
            if (half == 0) {
                float sg = shG[i * 64 + p];
                yh[(size_t)(base + i) * DINNER + h * DHEAD + p] =
                    __float2half((yv + dskip * u) * sg);
            }
        }
    }
}

// ---------------- launch ----------------
extern "C" void kernel_launch(void* const* d_in, const int* in_sizes, int n_in,
                              void* d_out, int out_size) {
    const float* x       = (const float*)d_in[0];
    const float* norm1_w = (const float*)d_in[1];
    const float* w_in    = (const float*)d_in[2];
    const float* conv_w  = (const float*)d_in[3];
    const float* w_bc    = (const float*)d_in[4];
    const float* D_skip  = (const float*)d_in[5];
    const float* w_out   = (const float*)d_in[6];
    const float* norm2_w = (const float*)d_in[7];
    const float* ff_w1   = (const float*)d_in[8];
    const float* ff_b1   = (const float*)d_in[9];
    const float* ff_w2   = (const float*)d_in[10];
    const float* ff_b2   = (const float*)d_in[11];
    float* out = (float*)d_out;

    float *bc, *Bn, *Cn, *coef, *par, *x1;
    __half *projh, *xnh, *vh, *yh, *hh, *ffh, *wh;
    cudaGetSymbolAddress((void**)&bc,    g_bc);
    cudaGetSymbolAddress((void**)&Bn,    g_Bn);
    cudaGetSymbolAddress((void**)&Cn,    g_Cn);
    cudaGetSymbolAddress((void**)&coef,  g_coef);
    cudaGetSymbolAddress((void**)&par,   g_par);
    cudaGetSymbolAddress((void**)&x1,    g_x1);
    cudaGetSymbolAddress((void**)&projh, g_projh);
    cudaGetSymbolAddress((void**)&xnh,   g_xnh);
    cudaGetSymbolAddress((void**)&vh,    g_vh);
    cudaGetSymbolAddress((void**)&yh,    g_yh);
    cudaGetSymbolAddress((void**)&hh,    g_hh);
    cudaGetSymbolAddress((void**)&ffh,   g_ffh);
    cudaGetSymbolAddress((void**)&wh,    g_wh);

    // dynamic smem sizes (halves * 2 bytes), 3 stages
    const int SM128 = STAGES * (128 * ASTRH + 128 * ASTRH) * 2;  // 61440 B
    const int SM64  = STAGES * (128 * ASTRH + 64 * ASTRH)  * 2;  // 46080 B
    cudaFuncSetAttribute(gemm_fp16<128, 64, 32, 5>,
                         cudaFuncAttributeMaxDynamicSharedMemorySize, SM128);
    cudaFuncSetAttribute(gemm_fp16<128, 64, 32, 1>,
                         cudaFuncAttributeMaxDynamicSharedMemorySize, SM128);
    cudaFuncSetAttribute(gemm_fp16<64, 32, 32, 0>,
                         cudaFuncAttributeMaxDynamicSharedMemorySize, SM64);
    cudaFuncSetAttribute(gemm_fp16<64, 32, 32, 2>,
                         cudaFuncAttributeMaxDynamicSharedMemorySize, SM64);
    cudaFuncSetAttribute(gemm_fp16<64, 32, 32, 3>,
                         cudaFuncAttributeMaxDynamicSharedMemorySize, SM64);

    // 0. all weight transposes -> [N][K] fp16, single launch
    transpose_all_kernel<<<T5_END, dim3(32, 8)>>>(
        w_in, w_bc, w_out, ff_w1, ff_w2, wh);

    // 1. rmsnorm1 -> fp16
    rmsnorm_kernel<<<BT, 256>>>(x, norm1_w, xnh);
    // 2. proj = xn @ w_in (4096 x 3120 x 768): silu(gate)|vraw fp16, params f32
    gemm_fp16<128, 64, 32, 5><<<dim3((DPROJ + 127) / 128, BT / 128), 256, SM128>>>(
        xnh, wh + W_IN_OFF, projh, BT, DPROJ, DMODEL, nullptr, nullptr, par);
    // 3. smem-tiled conv+silu -> fp16 v
    conv_silu_kernel<<<dim3(BT / 64, DINNER / 64), 256>>>(projh, conv_w, vh);
    // 4. bc = v @ w_bc (4096 x 384 x 1536), f32 out
    gemm_fp16<64, 32, 32, 0><<<dim3((2 * NHEADS * DSTATE) / 64, BT / 128), 256, SM64>>>(
        vh, wh + W_BC_OFF, bc, BT, 2 * NHEADS * DSTATE, DINNER, nullptr, nullptr, nullptr);
    // 5. normalize B/C + scan coefficients
    bcparams_kernel<<<(BT * NHEADS + 127) / 128, 128>>>(bc, par, Bn, Cn, coef);
    // 6. sequential scan (128 thr/block, 2 states/thread) -> fp16 y
    scan_kernel<<<BATCH * NHEADS, 128>>>(Bn, Cn, coef, vh, projh, D_skip, yh);
    // 7. x1 = x + y @ w_out (4096 x 768 x 1536), f32 out [BN=64: wave balance]
    gemm_fp16<64, 32, 32, 3><<<dim3(DMODEL / 64, BT / 128), 256, SM64>>>(
        yh, wh + W_OUT_OFF, x1, BT, DMODEL, DINNER, nullptr, x, nullptr);
    // 8. rmsnorm2 -> fp16
    rmsnorm_kernel<<<BT, 256>>>(x1, norm2_w, hh);
    // 9. ff = gelu(h @ ff_w1 + b1) (4096 x 3072 x 768), fp16 out
    gemm_fp16<128, 64, 32, 1><<<dim3(DFF / 128, BT / 128), 256, SM128>>>(
        hh, wh + FF1_OFF, ffh, BT, DFF, DMODEL, ff_b1, nullptr, nullptr);
    // 10. out = x1 + ff @ ff_w2 + b2 (4096 x 768 x 3072), f32 out [BN=64]
    gemm_fp16<64, 32, 32, 2><<<dim3(DMODEL / 64, BT / 128), 256, SM64>>>(
        ffh, wh + FF2_OFF, out, BT, DMODEL, DFF, ff_b2, x1, nullptr);
}

// round 16
// speedup vs baseline: 1.1283x; 1.0313x over previous
#include <cuda_runtime.h>
#include <cuda_fp16.h>
#include <math.h>
#include <stdint.h>

// ---------------- problem constants ----------------
#define BATCH   2
#define SEQ     2048
#define BT      (BATCH*SEQ)      // 4096 rows
#define DMODEL  768
#define DINNER  1536
#define NHEADS  24
#define DHEAD   64
#define DSTATE  8
#define DCONV   4
#define DPROJ   3120             // 2*DINNER + NHEADS*2
#define DGV     3072             // gate+vraw fp16 region width
#define NPAR    48               // params columns (f32 side buffer)
#define DFF     3072

// transposed weight scratch offsets (halves); layout [N][K]
#define W_IN_OFF  0
#define W_BC_OFF  2396160                       // 768*3120
#define W_OUT_OFF 2985984                       // + 1536*384
#define FF1_OFF   4165632                       // + 1536*768
#define FF2_OFF   6524928                       // + 768*3072
#define W_TOTAL   8884224                       // + 3072*768

// merged-transpose tile ranges (32x32 tiles, Nt = tiles along N)
#define T1_END 2352      // w_in : 98*24
#define T2_END 2928      // w_bc : 12*48
#define T3_END 4080      // w_out: 24*48
#define T4_END 6384      // ff1  : 96*24
#define T5_END 8688      // ff2  : 24*96

// ---------------- scratch (static device globals; no allocation) ----------------
__device__ float  g_bc  [BT*2*NHEADS*DSTATE];
__device__ float  g_Bn  [BT*NHEADS*DSTATE];
__device__ float  g_Cn  [BT*NHEADS*DSTATE];
__device__ float  g_coef[BT*NHEADS*4];
__device__ float  g_par [BT*NPAR];
__device__ float  g_x1  [BT*DMODEL];
__device__ __half g_projh[BT*DGV];            // silu(gate) | vraw (fp16)
__device__ __half g_xnh [BT*DMODEL];
__device__ __half g_vh  [BT*DINNER];
__device__ __half g_yh  [BT*DINNER];
__device__ __half g_hh  [BT*DMODEL];
__device__ __half g_ffh [BT*DFF];
__device__ __half g_wh  [W_TOTAL];

// ---------------- device math helpers ----------------
__device__ __forceinline__ float sigmoidf_(float x) { return 1.0f / (1.0f + expf(-x)); }
__device__ __forceinline__ float siluf_(float x)    { return x * sigmoidf_(x); }
__device__ __forceinline__ float softplusf_(float x){ return fmaxf(x, 0.0f) + log1pf(expf(-fabsf(x))); }
__device__ __forceinline__ float geluf_(float x) {
    float x3 = x * x * x;
    float t  = tanhf(0.7978845608028654f * (x + 0.044715f * x3));
    return 0.5f * x * (1.0f + t);
}

// ---------------- merged transpose+convert: all 5 weights, one launch --------
__global__ void transpose_all_kernel(const float* __restrict__ w_in,
                                     const float* __restrict__ w_bc,
                                     const float* __restrict__ w_out,
                                     const float* __restrict__ ff1,
                                     const float* __restrict__ ff2,
                                     __half* __restrict__ wh) {
    __shared__ float tile[32][33];
    int id = blockIdx.x;
    const float* src; __half* dst; int K, N, Nt;
    if (id < T1_END)      {            src = w_in;  dst = wh + W_IN_OFF;  K = DMODEL; N = DPROJ; Nt = 98; }
    else if (id < T2_END) { id -= T1_END; src = w_bc;  dst = wh + W_BC_OFF;  K = DINNER; N = 384;   Nt = 12; }
    else if (id < T3_END) { id -= T2_END; src = w_out; dst = wh + W_OUT_OFF; K = DINNER; N = DMODEL;Nt = 24; }
    else if (id < T4_END) { id -= T3_END; src = ff1;   dst = wh + FF1_OFF;   K = DMODEL; N = DFF;   Nt = 96; }
    else                  { id -= T4_END; src = ff2;   dst = wh + FF2_OFF;   K = DFF;    N = DMODEL;Nt = 24; }
    int nb = (id % Nt) * 32, kb = (id / Nt) * 32;
    int tx = threadIdx.x, ty = threadIdx.y;   // 32 x 8
#pragma unroll
    for (int j = 0; j < 32; j += 8) {
        int k = kb + ty + j, n = nb + tx;
        tile[ty + j][tx] = (k < K && n < N) ? src[(size_t)k * N + n] : 0.0f;
    }
    __syncthreads();
#pragma unroll
    for (int j = 0; j < 32; j += 8) {
        int n = nb + ty + j, k = kb + tx;
        if (n < N && k < K) dst[(size_t)n * K + k] = __float2half(tile[tx][ty + j]);
    }
}

// ---------------- rmsnorm: one block per row, fp16 output ----------------
__global__ void rmsnorm_kernel(const float* __restrict__ x,
                               const float* __restrict__ w,
                               __half* __restrict__ out) {
    int row = blockIdx.x;
    const float* xr = x + (size_t)row * DMODEL;
    __half*    orow = out + (size_t)row * DMODEL;

    float xv[3];
    float ss = 0.0f;
#pragma unroll
    for (int j = 0; j < 3; j++) {
        int i = threadIdx.x + j * 256;
        float v = xr[i];
        xv[j] = v;
        ss += v * v;
    }
#pragma unroll
    for (int off = 16; off > 0; off >>= 1)
        ss += __shfl_xor_sync(0xffffffff, ss, off);
    __shared__ float sh[8];
    int lane = threadIdx.x & 31, wid = threadIdx.x >> 5;
    if (lane == 0) sh[wid] = ss;
    __syncthreads();
    if (wid == 0) {
        float v = (lane < 8) ? sh[lane] : 0.0f;
#pragma unroll
        for (int off = 4; off > 0; off >>= 1)
            v += __shfl_xor_sync(0xffffffff, v, off);
        if (lane == 0) sh[0] = rsqrtf(v * (1.0f / DMODEL) + 1e-6f);
    }
    __syncthreads();
    float s = sh[0];
#pragma unroll
    for (int j = 0; j < 3; j++) {
        int i = threadIdx.x + j * 256;
        orow[i] = __float2half(xv[j] * s * w[i]);
    }
}

// ============================================================================
// fp16 mma.sync GEMM (m16n8k16), BK=64, 3-stage cp.async pipeline.
//   C[M,N] = A[M,K] @ Bt[N,K]^T ; A,Bt fp16, accumulate fp32.
//   BM=128, 256 threads (8 warps).
//   smem rows padded to 72 halves (144B; r*36 mod 32 distinct -> conflict-free).
//   EPI: 0 none(f32) | 1 half(gelu(acc+bias)) | 2 f32 acc+bias+res
//        | 3 f32 acc+res
//        | 5 proj split: col<DINNER -> silu->fp16, col<DGV -> fp16 (stride DGV),
//                        col>=DGV -> f32 aux[row*NPAR + col-DGV]
// ============================================================================
#define ASTRH  72
#define STAGES 3

template <int BN, int WM, int WN, int EPI>
__global__ void __launch_bounds__(256)
gemm_fp16(const __half* __restrict__ A,
          const __half* __restrict__ Bt,
          void* __restrict__ Cv,
          int M, int N, int K,
          const float* __restrict__ bias,
          const float* __restrict__ res,
          float* __restrict__ aux) {
    constexpr int MT   = WM / 16;
    constexpr int NT   = WN / 8;
    constexpr int WGM  = 128 / WM;
    constexpr int ASTG = 128 * ASTRH;
    constexpr int BSTG = BN * ASTRH;
    constexpr int BCH  = (BN * 8) / 256;       // B 16B-chunks per thread (2|4)

    extern __shared__ __half dsm[];
    __half* As = dsm;
    __half* Bs = dsm + STAGES * ASTG;

    const int tid  = threadIdx.x;
    const int warp = tid >> 5;
    const int lane = tid & 31;
    const int g    = lane >> 2;
    const int t    = lane & 3;
    const int sel  = lane >> 3;

    const int wm = (warp % WGM) * WM;
    const int wn = (warp / WGM) * WN;
    const int bm = blockIdx.y * 128;
    const int bn = blockIdx.x * BN;

    const int lrow  = wm + ((sel & 1) << 3) + (lane & 7);
    const int lcolh = (sel >> 1) << 3;
    const int brow  = ((sel >> 1) << 3) + (lane & 7);
    const int bcolh = (sel & 1) << 3;

    const uint32_t as0 = (uint32_t)__cvta_generic_to_shared(As);
    const uint32_t bs0 = (uint32_t)__cvta_generic_to_shared(Bs);

    float acc[MT][NT][4];
#pragma unroll
    for (int i = 0; i < MT; i++)
#pragma unroll
        for (int j = 0; j < NT; j++)
#pragma unroll
            for (int r = 0; r < 4; r++) acc[i][j][r] = 0.0f;

    const int nkt = K >> 6;       // BK = 64

    auto issue = [&](int kt, int buf) {
        int k0 = kt << 6;
        // A: 128 rows x 8 chunks(16B = 8 halves) = 1024 / 256 thr = 4 each
#pragma unroll
        for (int i = 0; i < 4; i++) {
            int idx = tid + (i << 8);
            int row = idx >> 3, c16 = idx & 7;
            const __half* src = &A[(size_t)(bm + row) * K + k0 + c16 * 8];
            uint32_t dst = as0 + (uint32_t)(buf * ASTG + row * ASTRH + c16 * 8) * 2u;
            asm volatile("cp.async.cg.shared.global [%0], [%1], 16;"
                         :: "r"(dst), "l"(src));
        }
#pragma unroll
        for (int i = 0; i < BCH; i++) {
            int idx = tid + (i << 8);
            int row = idx >> 3, c16 = idx & 7;
            int n = bn + row;
            const __half* src = &Bt[(size_t)(n < N ? n : 0) * K + k0 + c16 * 8];
            int sz = (n < N) ? 16 : 0;
            uint32_t dst = bs0 + (uint32_t)(buf * BSTG + row * ASTRH + c16 * 8) * 2u;
            asm volatile("cp.async.cg.shared.global [%0], [%1], 16, %2;"
                         :: "r"(dst), "l"(src), "r"(sz));
        }
        asm volatile("cp.async.commit_group;" ::: "memory");
    };

#pragma unroll
    for (int s = 0; s < STAGES - 1; ++s)
        if (s < nkt) issue(s, s);

    int buf = 0;
    for (int kt = 0; kt < nkt; ++kt) {
        asm volatile("cp.async.wait_group %0;" :: "n"(STAGES - 2) : "memory");
        __syncthreads();
        if (kt + STAGES - 1 < nkt)
            issue(kt + STAGES - 1, (kt + STAGES - 1) % STAGES);

#pragma unroll
        for (int ks = 0; ks < 4; ks++) {       // four k16 steps per BK=64
            uint32_t a[MT][4];
#pragma unroll
            for (int mi = 0; mi < MT; mi++) {
                uint32_t addr = as0 + (uint32_t)(buf * ASTG +
                                (lrow + mi * 16) * ASTRH + ks * 16 + lcolh) * 2u;
                asm volatile(
                    "ldmatrix.sync.aligned.m8n8.x4.shared.b16 {%0,%1,%2,%3}, [%4];"
                    : "=r"(a[mi][0]), "=r"(a[mi][1]), "=r"(a[mi][2]), "=r"(a[mi][3])
                    : "r"(addr));
            }
            uint32_t b[NT][2];
#pragma unroll
            for (int nt2 = 0; nt2 < NT / 2; nt2++) {
                uint32_t addr = bs0 + (uint32_t)(buf * BSTG +
                                (wn + nt2 * 16 + brow) * ASTRH + ks * 16 + bcolh) * 2u;
                asm volatile(
                    "ldmatrix.sync.aligned.m8n8.x4.shared.b16 {%0,%1,%2,%3}, [%4];"
                    : "=r"(b[nt2 * 2][0]), "=r"(b[nt2 * 2][1]),
                      "=r"(b[nt2 * 2 + 1][0]), "=r"(b[nt2 * 2 + 1][1])
                    : "r"(addr));
            }
#pragma unroll
            for (int ni = 0; ni < NT; ni++)
#pragma unroll
                for (int mi = 0; mi < MT; mi++) {
                    asm volatile(
                        "mma.sync.aligned.m16n8k16.row.col.f32.f16.f16.f32 "
                        "{%0,%1,%2,%3},{%4,%5,%6,%7},{%8,%9},{%0,%1,%2,%3};"
                        : "+f"(acc[mi][ni][0]), "+f"(acc[mi][ni][1]),
                          "+f"(acc[mi][ni][2]), "+f"(acc[mi][ni][3])
                        : "r"(a[mi][0]), "r"(a[mi][1]), "r"(a[mi][2]), "r"(a[mi][3]),
                          "r"(b[ni][0]), "r"(b[ni][1]));
                }
        }
        buf = (buf + 1 == STAGES) ? 0 : buf + 1;
    }

    // ---- epilogue ----
    float*  Cf = (float*)Cv;
    __half* Ch = (__half*)Cv;
#pragma unroll
    for (int mi = 0; mi < MT; mi++) {
        int row0 = bm + wm + mi * 16 + g;
        int row1 = row0 + 8;
#pragma unroll
        for (int ni = 0; ni < NT; ni++) {
            int col = bn + wn + ni * 8 + 2 * t;
            if (col < N) {
                float2 p0 = make_float2(acc[mi][ni][0], acc[mi][ni][1]);
                float2 p1 = make_float2(acc[mi][ni][2], acc[mi][ni][3]);
                if (EPI == 1) {
                    float b0v = bias[col], b1v = bias[col + 1];
                    *reinterpret_cast<__half2*>(&Ch[(size_t)row0 * N + col]) =
                        __floats2half2_rn(geluf_(p0.x + b0v), geluf_(p0.y + b1v));
                    *reinterpret_cast<__half2*>(&Ch[(size_t)row1 * N + col]) =
                        __floats2half2_rn(geluf_(p1.x + b0v), geluf_(p1.y + b1v));
                } else if (EPI == 5) {
                    if (col < DGV) {
                        if (col < DINNER) {
                            p0.x = siluf_(p0.x); p0.y = siluf_(p0.y);
                            p1.x = siluf_(p1.x); p1.y = siluf_(p1.y);
                        }
                        *reinterpret_cast<__half2*>(&Ch[(size_t)row0 * DGV + col]) =
                            __floats2half2_rn(p0.x, p0.y);
                        *reinterpret_cast<__half2*>(&Ch[(size_t)row1 * DGV + col]) =
                            __floats2half2_rn(p1.x, p1.y);
                    } else {
                        int pc = col - DGV;
                        *reinterpret_cast<float2*>(&aux[(size_t)row0 * NPAR + pc]) = p0;
                        *reinterpret_cast<float2*>(&aux[(size_t)row1 * NPAR + pc]) = p1;
                    }
                } else {
                    if (EPI == 2) {
                        float2 r0 = *reinterpret_cast<const float2*>(&res[(size_t)row0 * N + col]);
                        float2 r1 = *reinterpret_cast<const float2*>(&res[(size_t)row1 * N + col]);
                        p0.x += bias[col] + r0.x; p0.y += bias[col + 1] + r0.y;
                        p1.x += bias[col] + r1.x; p1.y += bias[col + 1] + r1.y;
                    } else if (EPI == 3) {
                        float2 r0 = *reinterpret_cast<const float2*>(&res[(size_t)row0 * N + col]);
                        float2 r1 = *reinterpret_cast<const float2*>(&res[(size_t)row1 * N + col]);
                        p0.x += r0.x; p0.y += r0.y;
                        p1.x += r1.x; p1.y += r1.y;
                    }
                    *reinterpret_cast<float2*>(&Cf[(size_t)row0 * N + col]) = p0;
                    *reinterpret_cast<float2*>(&Cf[(size_t)row1 * N + col]) = p1;
                }
            }
        }
    }
}

// ---------------- smem-tiled conv+silu -> fp16 v (fp16 vraw input) -----------
__global__ void __launch_bounds__(256)
conv_silu_kernel(const __half* __restrict__ projh,
                 const float* __restrict__ conv_w,
                 __half* __restrict__ vh) {
    __shared__ float shP[67 * 64];
    __shared__ float shW[4][64];
    const int tid = threadIdx.x;          // 0..255
    const int bt0 = blockIdx.x * 64;
    const int c0  = blockIdx.y * 64;
    const bool seqstart = (bt0 % SEQ) == 0;

    {   // conv weights: 64 channels x 4 taps
        int c = tid >> 2, k = tid & 3;
        shW[k][c] = conv_w[(c0 + c) * DCONV + k];
    }
#pragma unroll
    for (int pass = 0; pass < 3; pass++) {
        int idx = pass * 256 + tid;
        if (idx < 67 * 8) {
            int j = idx >> 3, hc = idx & 7;
            uint4 hv = make_uint4(0u, 0u, 0u, 0u);
            if (!(seqstart && j < 3))
                hv = *reinterpret_cast<const uint4*>(
                    &projh[(size_t)(bt0 - 3 + j) * DGV + DINNER + c0 + hc * 8]);
            const __half2* hp = reinterpret_cast<const __half2*>(&hv);
            float* dp = &shP[j * 64 + hc * 8];
#pragma unroll
            for (int q = 0; q < 4; q++) {
                float2 f = __half22float2(hp[q]);
                dp[2 * q]     = f.x;
                dp[2 * q + 1] = f.y;
            }
        }
    }
    __syncthreads();
#pragma unroll
    for (int pass = 0; pass < 16; pass++) {
        int idx = pass * 256 + tid;
        int r = idx >> 6, c = idx & 63;
        float acc = 0.0f;
#pragma unroll
        for (int k = 0; k < 4; k++)
            acc = fmaf(shP[(r + k) * 64 + c], shW[k][c], acc);
        vh[(size_t)(bt0 + r) * DINNER + c0 + c] = __float2half(siluf_(acc));
    }
}

// ---------------- B/C normalize + scan coefficients (f32 params) -------------
__global__ void bcparams_kernel(const float* __restrict__ bc,
                                const float* __restrict__ par,
                                float* __restrict__ Bn,
                                float* __restrict__ Cn,
                                float* __restrict__ coef) {
    int idx = blockIdx.x * blockDim.x + threadIdx.x;
    if (idx >= BT * NHEADS) return;
    int h  = idx % NHEADS;
    int bt = idx / NHEADS;

    const float* p = bc + (size_t)bt * (2 * NHEADS * DSTATE) + h * 16;
    float bl[8], cl[8];
    float ssb = 0.0f, ssc = 0.0f;
#pragma unroll
    for (int n = 0; n < 8; n++) {
        bl[n] = p[n];     ssb = fmaf(bl[n], bl[n], ssb);
        cl[n] = p[8 + n]; ssc = fmaf(cl[n], cl[n], ssc);
    }
    float rb = rsqrtf(ssb + 1e-12f);
    float rc = rsqrtf(ssc + 1e-12f);
#pragma unroll
    for (int n = 0; n < 8; n++) {
        Bn[(size_t)idx * 8 + n] = bl[n] * rb;
        Cn[(size_t)idx * 8 + n] = cl[n] * rc;
    }
    float p0 = par[(size_t)bt * NPAR + h * 2 + 0];
    float p1 = par[(size_t)bt * NPAR + h * 2 + 1];
    float Aq = softplusf_(p0);
    float dt = sigmoidf_(p1);
    float S  = 1.0f / (1.0f + dt * dt * Aq);
    coef[(size_t)idx * 4 + 0] = S;
    coef[(size_t)idx * 4 + 1] = S * dt * Aq;
    coef[(size_t)idx * 4 + 2] = S * dt;
    coef[(size_t)idx * 4 + 3] = dt;
}

// ---------------- sequential LinOSS-IM scan, 128 threads/block ---------------
__global__ void scan_kernel(const float* __restrict__ Bn,
                            const float* __restrict__ Cn,
                            const float* __restrict__ coef,
                            const __half* __restrict__ vh,
                            const __half* __restrict__ projh,  // gate silu'd fp16
                            const float* __restrict__ Dsk,
                            __half* __restrict__ yh) {
    int bh = blockIdx.x;                  // 0..47
    int b = bh / NHEADS, h = bh % NHEADS;
    int tid  = threadIdx.x;               // 0..127
    int p    = tid >> 1;                   // 0..63
    int half = tid & 1;                    // state half
    float dskip = Dsk[h];

    __shared__ float4 shB[64 * 2];
    __shared__ float4 shC[64 * 2];
    __shared__ float4 shCo[64];
    __shared__ float  shU[64 * 64];
    __shared__ float  shG[64 * 64];

    float z[4], xs[4];
#pragma unroll
    for (int n = 0; n < 4; n++) { z[n] = 0.0f; xs[n] = 0.0f; }

    for (int chunk = 0; chunk < SEQ / 64; chunk++) {
        __syncthreads();
        {
            int tB  = chunk * 64 + p;
            int idx = (b * SEQ + tB) * NHEADS + h;
            shB[p * 2 + half] = *reinterpret_cast<const float4*>(&Bn[(size_t)idx * 8 + half * 4]);
            shC[p * 2 + half] = *reinterpret_cast<const float4*>(&Cn[(size_t)idx * 8 + half * 4]);
            if (half == 0)
                shCo[p] = *reinterpret_cast<const float4*>(&coef[(size_t)idx * 4]);
        }
        int base = b * SEQ + chunk * 64;
#pragma unroll
        for (int pass = 0; pass < 4; pass++) {
            int idx = pass * 128 + tid;
            int row = idx >> 3, hc = idx & 7;
            uint4 hv = *reinterpret_cast<const uint4*>(
                &vh[(size_t)(base + row) * DINNER + h * DHEAD + hc * 8]);
            const __half2* hp = reinterpret_cast<const __half2*>(&hv);
            float* du = &shU[row * 64 + hc * 8];
#pragma unroll
            for (int j = 0; j < 4; j++) {
                float2 f = __half22float2(hp[j]);
                du[2 * j]     = f.x;
                du[2 * j + 1] = f.y;
            }
        }
#pragma unroll
        for (int pass = 0; pass < 4; pass++) {
            int idx = pass * 128 + tid;
            int row = idx >> 3, hc = idx & 7;
            uint4 hv = *reinterpret_cast<const uint4*>(
                &projh[(size_t)(base + row) * DGV + h * DHEAD + hc * 8]);
            const __half2* hp = reinterpret_cast<const __half2*>(&hv);
            float* dg = &shG[row * 64 + hc * 8];
#pragma unroll
            for (int j = 0; j < 4; j++) {
                float2 f = __half22float2(hp[j]);
                dg[2 * j]     = f.x;
                dg[2 * j + 1] = f.y;
            }
        }
        __syncthreads();

#pragma unroll 4
        for (int i = 0; i < 64; i++) {
            float4 co = shCo[i];
            float  u  = shU[i * 64 + p];
            float4 bv = shB[i * 2 + half];
            float4 cv = shC[i * 2 + half];
            float bb[4] = {bv.x, bv.y, bv.z, bv.w};
            float cc[4] = {cv.x, cv.y, cv.z, cv.w};
            float yv = 0.0f;
#pragma unroll
            for (int n = 0; n < 4; n++) {
                z[n]  = fmaf(co.x, z[n], fmaf(-co.y, xs[n], co.z * bb[n] * u));
                xs[n] = fmaf(co.w, z[n], xs[n]);
                yv    = fmaf(cc[n], xs[n], yv);
            }
            yv += __shfl_xor_sync(0xffffffff, yv, 1);
            if (half == 0) {
                float sg = shG[i * 64 + p];
                yh[(size_t)(base + i) * DINNER + h * DHEAD + p] =
                    __float2half((yv + dskip * u) * sg);
            }
        }
    }
}

// ---------------- launch ----------------
extern "C" void kernel_launch(void* const* d_in, const int* in_sizes, int n_in,
                              void* d_out, int out_size) {
    const float* x       = (const float*)d_in[0];
    const float* norm1_w = (const float*)d_in[1];
    const float* w_in    = (const float*)d_in[2];
    const float* conv_w  = (const float*)d_in[3];
    const float* w_bc    = (const float*)d_in[4];
    const float* D_skip  = (const float*)d_in[5];
    const float* w_out   = (const float*)d_in[6];
    const float* norm2_w = (const float*)d_in[7];
    const float* ff_w1   = (const float*)d_in[8];
    const float* ff_b1   = (const float*)d_in[9];
    const float* ff_w2   = (const float*)d_in[10];
    const float* ff_b2   = (const float*)d_in[11];
    float* out = (float*)d_out;

    float *bc, *Bn, *Cn, *coef, *par, *x1;
    __half *projh, *xnh, *vh, *yh, *hh, *ffh, *wh;
    cudaGetSymbolAddress((void**)&bc,    g_bc);
    cudaGetSymbolAddress((void**)&Bn,    g_Bn);
    cudaGetSymbolAddress((void**)&Cn,    g_Cn);
    cudaGetSymbolAddress((void**)&coef,  g_coef);
    cudaGetSymbolAddress((void**)&par,   g_par);
    cudaGetSymbolAddress((void**)&x1,    g_x1);
    cudaGetSymbolAddress((void**)&projh, g_projh);
    cudaGetSymbolAddress((void**)&xnh,   g_xnh);
    cudaGetSymbolAddress((void**)&vh,    g_vh);
    cudaGetSymbolAddress((void**)&yh,    g_yh);
    cudaGetSymbolAddress((void**)&hh,    g_hh);
    cudaGetSymbolAddress((void**)&ffh,   g_ffh);
    cudaGetSymbolAddress((void**)&wh,    g_wh);

    // dynamic smem sizes (halves * 2 bytes), 3 stages, BK=64
    const int SM128 = STAGES * (128 * ASTRH + 128 * ASTRH) * 2;  // 110592 B
    const int SM64  = STAGES * (128 * ASTRH + 64 * ASTRH)  * 2;  // 82944 B
    cudaFuncSetAttribute(gemm_fp16<128, 64, 32, 5>,
                         cudaFuncAttributeMaxDynamicSharedMemorySize, SM128);
    cudaFuncSetAttribute(gemm_fp16<128, 64, 32, 1>,
                         cudaFuncAttributeMaxDynamicSharedMemorySize, SM128);
    cudaFuncSetAttribute(gemm_fp16<64, 32, 32, 0>,
                         cudaFuncAttributeMaxDynamicSharedMemorySize, SM64);
    cudaFuncSetAttribute(gemm_fp16<64, 32, 32, 2>,
                         cudaFuncAttributeMaxDynamicSharedMemorySize, SM64);
    cudaFuncSetAttribute(gemm_fp16<64, 32, 32, 3>,
                         cudaFuncAttributeMaxDynamicSharedMemorySize, SM64);

    // 0. all weight transposes -> [N][K] fp16, single launch
    transpose_all_kernel<<<T5_END, dim3(32, 8)>>>(
        w_in, w_bc, w_out, ff_w1, ff_w2, wh);

    // 1. rmsnorm1 -> fp16
    rmsnorm_kernel<<<BT, 256>>>(x, norm1_w, xnh);
    // 2. proj = xn @ w_in (4096 x 3120 x 768): silu(gate)|vraw fp16, params f32
    gemm_fp16<128, 64, 32, 5><<<dim3((DPROJ + 127) / 128, BT / 128), 256, SM128>>>(
        xnh, wh + W_IN_OFF, projh, BT, DPROJ, DMODEL, nullptr, nullptr, par);
    // 3. smem-tiled conv+silu -> fp16 v
    conv_silu_kernel<<<dim3(BT / 64, DINNER / 64), 256>>>(projh, conv_w, vh);
    // 4. bc = v @ w_bc (4096 x 384 x 1536), f32 out
    gemm_fp16<64, 32, 32, 0><<<dim3((2 * NHEADS * DSTATE) / 64, BT / 128), 256, SM64>>>(
        vh, wh + W_BC_OFF, bc, BT, 2 * NHEADS * DSTATE, DINNER, nullptr, nullptr, nullptr);
    // 5. normalize B/C + scan coefficients
    bcparams_kernel<<<(BT * NHEADS + 127) / 128, 128>>>(bc, par, Bn, Cn, coef);
    // 6. sequential scan (128 thr/block, 2 states/thread) -> fp16 y
    scan_kernel<<<BATCH * NHEADS, 128>>>(Bn, Cn, coef, vh, projh, D_skip, yh);
    // 7. x1 = x + y @ w_out (4096 x 768 x 1536), f32 out [BN=64: wave balance]
    gemm_fp16<64, 32, 32, 3><<<dim3(DMODEL / 64, BT / 128), 256, SM64>>>(
        yh, wh + W_OUT_OFF, x1, BT, DMODEL, DINNER, nullptr, x, nullptr);
    // 8. rmsnorm2 -> fp16
    rmsnorm_kernel<<<BT, 256>>>(x1, norm2_w, hh);
    // 9. ff = gelu(h @ ff_w1 + b1) (4096 x 3072 x 768), fp16 out
    gemm_fp16<128, 64, 32, 1><<<dim3(DFF / 128, BT / 128), 256, SM128>>>(
        hh, wh + FF1_OFF, ffh, BT, DFF, DMODEL, ff_b1, nullptr, nullptr);
    // 10. out = x1 + ff @ ff_w2 + b2 (4096 x 768 x 3072), f32 out [BN=64]
    gemm_fp16<64, 32, 32, 2><<<dim3(DMODEL / 64, BT / 128), 256, SM64>>>(
        ffh, wh + FF2_OFF, out, BT, DMODEL, DFF, ff_b2, x1, nullptr);
}